// round 7
// baseline (speedup 1.0000x reference)
#include <cuda_runtime.h>
#include <cuda_fp16.h>
#include <math.h>

#define T_TOK 512
#define N_RES 4096
#define C_DIM 384
#define H_HEADS 8
#define KD 48
#define F_DIM 1536
#define LN_EPS 1e-5f
#define BIGF 1e9f
#define RSPLIT 4
#define RCHUNK 64
#define STAGES 3

typedef __half hf;

// ---------------- scratch (device globals) ----------------
__device__ hf    g_qin [T_TOK * C_DIM];
__device__ hf    g_din [N_RES * C_DIM];
__device__ hf    g_ln4 [N_RES * C_DIM];
__device__ float g_q   [T_TOK * C_DIM];
__device__ float g_gate[T_TOK * C_DIM];
__device__ float g_k   [N_RES * C_DIM];
__device__ float g_v   [N_RES * C_DIM];
__device__ hf    g_wag [T_TOK * C_DIM];
__device__ hf    g_ln3 [T_TOK * C_DIM];
__device__ hf    g_h1  [T_TOK * F_DIM];
__device__ hf    g_h2  [N_RES * F_DIM];
// fp16 TRANSPOSED weights Wt[N][K] (element offsets)
#define OFF_QW  0
#define OFF_KW  147456
#define OFF_VW  294912
#define OFF_GW  442368
#define OFF_OW  589824
#define OFF_RT1 737280
#define OFF_RT2 1327104
#define OFF_OT1 1916928
#define OFF_OT2 2506752
#define WTS_TOTAL 3096576
__device__ hf g_wts[WTS_TOTAL];
// flash partials
__device__ float g_po[RSPLIT * H_HEADS * T_TOK * KD];
__device__ float g_pm[RSPLIT * H_HEADS * T_TOK];
__device__ float g_pl[RSPLIT * H_HEADS * T_TOK];

__device__ __forceinline__ float to_tf32(float x) {
    asm("cvt.rna.tf32.f32 %0, %1;" : "=f"(x) : "f"(x));
    return x;
}

#define MMA_TF32(c, a, b) \
    asm volatile("mma.sync.aligned.m16n8k8.row.col.f32.tf32.tf32.f32 " \
        "{%0,%1,%2,%3}, {%4,%5,%6,%7}, {%8,%9}, {%0,%1,%2,%3};" \
        : "+f"((c)[0]), "+f"((c)[1]), "+f"((c)[2]), "+f"((c)[3]) \
        : "r"((a)[0]), "r"((a)[1]), "r"((a)[2]), "r"((a)[3]), \
          "r"((b)[0]), "r"((b)[1]))

#define MMA_F16(c, a, b) \
    asm volatile("mma.sync.aligned.m16n8k16.row.col.f32.f16.f16.f32 " \
        "{%0,%1,%2,%3}, {%4,%5,%6,%7}, {%8,%9}, {%0,%1,%2,%3};" \
        : "+f"((c)[0]), "+f"((c)[1]), "+f"((c)[2]), "+f"((c)[3]) \
        : "r"((a)[0]), "r"((a)[1]), "r"((a)[2]), "r"((a)[3]), \
          "r"((b)[0]), "r"((b)[1]))

__device__ __forceinline__ void ldsm4(unsigned& r0, unsigned& r1, unsigned& r2, unsigned& r3,
                                      unsigned addr) {
    asm volatile("ldmatrix.sync.aligned.m8n8.x4.shared.b16 {%0,%1,%2,%3}, [%4];"
        : "=r"(r0), "=r"(r1), "=r"(r2), "=r"(r3) : "r"(addr));
}

__device__ __forceinline__ void cp16(void* dst, const void* src) {
    unsigned d = (unsigned)__cvta_generic_to_shared(dst);
    asm volatile("cp.async.ca.shared.global [%0], [%1], 16;" :: "r"(d), "l"(src));
}
#define CP_COMMIT() asm volatile("cp.async.commit_group;")
#define CP_WAIT(n)  asm volatile("cp.async.wait_group %0;" :: "n"(n))

// ---------------- weight transpose + fp16 convert: W[K][N] fp32 -> Wt[N][K] fp16 ----------------
struct SrcPtrs { const float* p[9]; };

__global__ __launch_bounds__(256) void wt_kernel(SrcPtrs s, hf* __restrict__ dst) {
    const int segK[9]   = {384, 384, 384, 384, 384, 384, 1536, 384, 1536};
    const int segN[9]   = {384, 384, 384, 384, 384, 1536, 384, 1536, 384};
    const int segOff[9] = {OFF_QW, OFF_KW, OFF_VW, OFF_GW, OFF_OW, OFF_RT1, OFF_RT2, OFF_OT1, OFF_OT2};
    const int cum[10]   = {0, 144, 288, 432, 576, 720, 1296, 1872, 2448, 3024};
    int b = blockIdx.x;
    int seg = 0;
    #pragma unroll
    for (int i = 1; i < 9; i++) if (b >= cum[i]) seg = i;
    int tile = b - cum[seg];
    int K = segK[seg], N = segN[seg];
    int ntn = N >> 5;
    int k0 = (tile / ntn) * 32, n0 = (tile % ntn) * 32;
    const float* src = s.p[seg];

    __shared__ float smt[32][33];
    int t = threadIdx.x;
    int r = t >> 3, c4 = (t & 7) * 4;
    float4 v = *reinterpret_cast<const float4*>(&src[(size_t)(k0 + r) * N + n0 + c4]);
    smt[r][c4 + 0] = v.x; smt[r][c4 + 1] = v.y;
    smt[r][c4 + 2] = v.z; smt[r][c4 + 3] = v.w;
    __syncthreads();
    int n = t >> 3, k4 = (t & 7) * 4;
    __half2 lo = __floats2half2_rn(smt[k4 + 0][n], smt[k4 + 1][n]);
    __half2 hi = __floats2half2_rn(smt[k4 + 2][n], smt[k4 + 3][n]);
    hf* d = dst + segOff[seg] + (size_t)(n0 + n) * K + k0 + k4;
    *reinterpret_cast<__half2*>(d)     = lo;
    *reinterpret_cast<__half2*>(d + 2) = hi;
}

// ---------------- LayerNorm core: one 128-thr block per row of 384, fp16 output ----------------
__device__ __forceinline__ void ln_row(const float* __restrict__ xr,
                                       const float* __restrict__ scale,
                                       const float* __restrict__ offset,
                                       hf* __restrict__ orow) {
    int t = threadIdx.x;
    float v0 = xr[t], v1 = xr[t + 128], v2 = xr[t + 256];
    float s  = v0 + v1 + v2;
    float s2 = v0 * v0 + v1 * v1 + v2 * v2;
    #pragma unroll
    for (int o = 16; o; o >>= 1) {
        s  += __shfl_down_sync(0xffffffffu, s,  o);
        s2 += __shfl_down_sync(0xffffffffu, s2, o);
    }
    __shared__ float sh[8];
    __shared__ float mu_s, rstd_s;
    int wid = t >> 5, lane = t & 31;
    if (lane == 0) { sh[wid] = s; sh[4 + wid] = s2; }
    __syncthreads();
    if (t == 0) {
        float ts  = sh[0] + sh[1] + sh[2] + sh[3];
        float ts2 = sh[4] + sh[5] + sh[6] + sh[7];
        float mu  = ts * (1.0f / C_DIM);
        float var = ts2 * (1.0f / C_DIM) - mu * mu;
        mu_s = mu; rstd_s = rsqrtf(var + LN_EPS);
    }
    __syncthreads();
    float mu = mu_s, rstd = rstd_s;
    orow[t]       = __float2half_rn(scale[t]       * (v0 - mu) * rstd + offset[t]);
    orow[t + 128] = __float2half_rn(scale[t + 128] * (v1 - mu) * rstd + offset[t + 128]);
    orow[t + 256] = __float2half_rn(scale[t + 256] * (v2 - mu) * rstd + offset[t + 256]);
}

__global__ void ln_kernel(const float* __restrict__ x, const float* __restrict__ scale,
                          const float* __restrict__ offset, hf* __restrict__ out) {
    int row = blockIdx.x;
    ln_row(x + (size_t)row * C_DIM, scale, offset, out + (size_t)row * C_DIM);
}

__global__ void ln_fused_kernel(const float* __restrict__ resampled, const float* __restrict__ original,
                                const float* __restrict__ qn_s, const float* __restrict__ qn_o,
                                const float* __restrict__ dn_s, const float* __restrict__ dn_o,
                                const float* __restrict__ ot_s, const float* __restrict__ ot_o,
                                hf* __restrict__ qin, hf* __restrict__ din, hf* __restrict__ ln4) {
    int row = blockIdx.x;
    if (row < T_TOK) {
        ln_row(resampled + (size_t)row * C_DIM, qn_s, qn_o, qin + (size_t)row * C_DIM);
    } else if (row < T_TOK + N_RES) {
        int r = row - T_TOK;
        ln_row(original + (size_t)r * C_DIM, dn_s, dn_o, din + (size_t)r * C_DIM);
    } else {
        int r = row - T_TOK - N_RES;
        ln_row(original + (size_t)r * C_DIM, ot_s, ot_o, ln4 + (size_t)r * C_DIM);
    }
}

// ---------------- 128x128x64 fp16 GEMM, 3-stage cp.async, ldmatrix, m16n8k16 ----------------
// A[M][K] fp16, B = Wt[N][K] fp16. out modes: 0=f32(+res), 1=f32 tf32-rounded(+res), 2=fp16
#define ACT_NONE 0
#define ACT_RELU 1
#define ACT_SIGMOID 2
#define STAGE_BYTES 16384   // 128*64 halves * 2B

__global__ __launch_bounds__(256, 2) void gemm_hf(
    const hf* __restrict__ A,
    const hf* __restrict__ B0, void* __restrict__ C0v, float alpha0,
    const float* __restrict__ bias0, int act0, const float* __restrict__ res0, int mode0,
    const hf* __restrict__ B1, void* __restrict__ C1v, float alpha1,
    const float* __restrict__ bias1, int act1, const float* __restrict__ res1, int mode1,
    int M, int N, int K, int halfX) {
    extern __shared__ hf smg[];
    hf* As = smg;                       // STAGES * 8192 halves
    hf* Bs = smg + STAGES * 8192;
    unsigned sa_base = (unsigned)__cvta_generic_to_shared(As);
    unsigned sb_base = (unsigned)__cvta_generic_to_shared(Bs);

    int t = threadIdx.x;
    int bxx = blockIdx.x;
    const hf* B = B0; void* Cv = C0v; float alpha = alpha0;
    const float* bias = bias0; int act = act0; const float* residual = res0; int mode = mode0;
    if (bxx >= halfX) {
        bxx -= halfX;
        B = B1; Cv = C1v; alpha = alpha1; bias = bias1; act = act1; residual = res1; mode = mode1;
    }
    int bm = blockIdx.y * 128, bn = bxx * 128;
    int wid = t >> 5, lane = t & 31, grp = lane >> 2, tig = lane & 3;
    int wm = (wid >> 2) * 64;
    int wn = (wid & 3) * 32;

    // cp.async load mapping: 1024 granules (16B = 8 halves) per tile
    int a_dst[4];
    size_t a_src[4], b_src[4];
    #pragma unroll
    for (int i = 0; i < 4; i++) {
        int idx = t + i * 256;
        int m = idx >> 3, g = idx & 7;
        a_dst[i] = (m * 8 + (g ^ (m & 7))) * 8;
        a_src[i] = (size_t)(bm + m) * K + g * 8;
        b_src[i] = (size_t)(bn + m) * K + g * 8;
    }

    // ldmatrix per-lane row byte-offsets
    int r8 = lane & 7, j = lane >> 3;
    unsigned a_ro[4], b_ro[2];
    #pragma unroll
    for (int fm = 0; fm < 4; fm++)
        a_ro[fm] = (unsigned)(wm + fm * 16 + ((j & 1) << 3) + r8) * 128;
    #pragma unroll
    for (int p = 0; p < 2; p++)
        b_ro[p] = (unsigned)(wn + p * 16 + ((j >> 1) << 3) + r8) * 128;

    float acc[4][4][4];
    #pragma unroll
    for (int i = 0; i < 4; i++)
        #pragma unroll
        for (int jj = 0; jj < 4; jj++)
            #pragma unroll
            for (int r = 0; r < 4; r++) acc[i][jj][r] = 0.0f;

    int kTiles = K >> 6;

    #pragma unroll
    for (int pt = 0; pt < STAGES - 1; pt++) {
        hf* ab = As + pt * 8192;
        hf* bb = Bs + pt * 8192;
        #pragma unroll
        for (int i = 0; i < 4; i++) {
            cp16(ab + a_dst[i], A + a_src[i] + pt * 64);
            cp16(bb + a_dst[i], B + b_src[i] + pt * 64);
        }
        CP_COMMIT();
    }

    for (int kt = 0; kt < kTiles; kt++) {
        CP_WAIT(STAGES - 2);
        __syncthreads();
        int nt = kt + STAGES - 1;
        if (nt < kTiles) {
            int buf = nt % STAGES;
            hf* ab = As + buf * 8192;
            hf* bb = Bs + buf * 8192;
            #pragma unroll
            for (int i = 0; i < 4; i++) {
                cp16(ab + a_dst[i], A + a_src[i] + nt * 64);
                cp16(bb + a_dst[i], B + b_src[i] + nt * 64);
            }
        }
        CP_COMMIT();
        unsigned aB = sa_base + (kt % STAGES) * STAGE_BYTES;
        unsigned bB = sb_base + (kt % STAGES) * STAGE_BYTES;
        #pragma unroll
        for (int s = 0; s < 4; s++) {           // 4 x k16 steps
            unsigned ga = (unsigned)(((2 * s + (j >> 1)) ^ r8) << 4);
            unsigned gb = (unsigned)(((2 * s + (j & 1)) ^ r8) << 4);
            unsigned af[4][4];
            #pragma unroll
            for (int fm = 0; fm < 4; fm++)
                ldsm4(af[fm][0], af[fm][1], af[fm][2], af[fm][3], aB + a_ro[fm] + ga);
            unsigned bfr[4][2];
            #pragma unroll
            for (int p = 0; p < 2; p++) {
                unsigned b0, b1, b2, b3;
                ldsm4(b0, b1, b2, b3, bB + b_ro[p] + gb);
                bfr[2 * p][0] = b0; bfr[2 * p][1] = b1;
                bfr[2 * p + 1][0] = b2; bfr[2 * p + 1][1] = b3;
            }
            #pragma unroll
            for (int fm = 0; fm < 4; fm++)
                #pragma unroll
                for (int fn = 0; fn < 4; fn++)
                    MMA_F16(acc[fm][fn], af[fm], bfr[fn]);
        }
    }

    __syncthreads();   // protect smem reuse boundary before epilogue returns (none) — cheap
    #pragma unroll
    for (int fm = 0; fm < 4; fm++) {
        #pragma unroll
        for (int fn = 0; fn < 4; fn++) {
            int m0 = bm + wm + fm * 16 + grp;
            int n  = bn + wn + fn * 8 + tig * 2;
            #pragma unroll
            for (int half = 0; half < 2; half++) {
                int m = m0 + half * 8;
                float x0 = acc[fm][fn][half * 2 + 0] * alpha;
                float x1 = acc[fm][fn][half * 2 + 1] * alpha;
                if (bias) { x0 += bias[n]; x1 += bias[n + 1]; }
                if (act == ACT_RELU) {
                    x0 = fmaxf(x0, 0.0f); x1 = fmaxf(x1, 0.0f);
                } else if (act == ACT_SIGMOID) {
                    x0 = 1.0f / (1.0f + __expf(-x0));
                    x1 = 1.0f / (1.0f + __expf(-x1));
                }
                if (mode == 2) {
                    hf* Cb = (hf*)Cv;
                    *reinterpret_cast<__half2*>(&Cb[(size_t)m * N + n]) =
                        __floats2half2_rn(x0, x1);
                } else {
                    float* Cf = (float*)Cv;
                    if (residual) {
                        float2 r = *reinterpret_cast<const float2*>(&residual[(size_t)m * N + n]);
                        x0 += r.x; x1 += r.y;
                    }
                    if (mode == 1) { x0 = to_tf32(x0); x1 = to_tf32(x1); }
                    *reinterpret_cast<float2*>(&Cf[(size_t)m * N + n]) = make_float2(x0, x1);
                }
            }
        }
    }
}

// ---------------- flash attention (tf32, unchanged) ----------------
#define QS_PITCH 52
#define VS_PITCH 56
#define MS_PITCH 68
#define FL_QS 0
#define FL_KS (64*52)
#define FL_VS (FL_KS + 2*64*52)
#define FL_MS (FL_VS + 2*64*56)
#define FL_TOTAL (FL_MS + 2*64*68)

__global__ __launch_bounds__(128) void flash_kernel(
    const float* __restrict__ q, const float* __restrict__ k,
    const float* __restrict__ v, const float* __restrict__ mask,
    float* __restrict__ po, float* __restrict__ pm, float* __restrict__ pl) {
    extern __shared__ float sm[];
    float* Qs = sm + FL_QS;
    int t = threadIdx.x;
    int wid = t >> 5, lane = t & 31, grp = lane >> 2, tig = lane & 3;
    int t0 = blockIdx.x * 64;
    int h  = blockIdx.y;
    int rsp = blockIdx.z;
    int rbase = rsp * (N_RES / RSPLIT);
    int wr = wid * 16;

    for (int i = t; i < 64 * 12; i += 128) {
        int r = i / 12, f = i % 12;
        float4 q4 = *reinterpret_cast<const float4*>(&q[(size_t)(t0 + r) * C_DIM + h * KD + f * 4]);
        *reinterpret_cast<float4*>(&Qs[r * QS_PITCH + f * 4]) = q4;
    }

    const int NCH = (N_RES / RSPLIT) / RCHUNK;   // 16

    auto issue = [&](int ch, int b) {
        int r0 = rbase + ch * RCHUNK;
        float* ks = sm + FL_KS + b * 64 * QS_PITCH;
        float* vs = sm + FL_VS + b * 64 * VS_PITCH;
        float* ms = sm + FL_MS + b * 64 * MS_PITCH;
        for (int i = t; i < 64 * 12; i += 128) {
            int r = i / 12, f = i % 12;
            size_t src = (size_t)(r0 + r) * C_DIM + h * KD + f * 4;
            cp16(&ks[r * QS_PITCH + f * 4], &k[src]);
            cp16(&vs[r * VS_PITCH + f * 4], &v[src]);
        }
        for (int i = t; i < 64 * 16; i += 128) {
            int rr = i / 16, f = i % 16;
            cp16(&ms[rr * MS_PITCH + f * 4],
                 &mask[((size_t)h * T_TOK + t0 + rr) * N_RES + r0 + f * 4]);
        }
    };

    issue(0, 0); CP_COMMIT();
    issue(1, 1); CP_COMMIT();

    float m_lo = -1e30f, m_hi = -1e30f, l_lo = 0.0f, l_hi = 0.0f;
    float acc_o[6][4];
    #pragma unroll
    for (int i = 0; i < 6; i++)
        #pragma unroll
        for (int e = 0; e < 4; e++) acc_o[i][e] = 0.0f;

    for (int ch = 0; ch < NCH; ch++) {
        int b = ch & 1;
        CP_WAIT(1);
        __syncthreads();
        float* ks = sm + FL_KS + b * 64 * QS_PITCH;
        float* vs = sm + FL_VS + b * 64 * VS_PITCH;
        float* ms = sm + FL_MS + b * 64 * MS_PITCH;

        float acc_s[8][4];
        #pragma unroll
        for (int fn = 0; fn < 8; fn++)
            #pragma unroll
            for (int e = 0; e < 4; e++) acc_s[fn][e] = 0.0f;
        #pragma unroll
        for (int s = 0; s < 6; s++) {
            int k0 = s * 8;
            unsigned a[4];
            a[0] = __float_as_uint(Qs[(wr + grp) * QS_PITCH + k0 + tig]);
            a[1] = __float_as_uint(Qs[(wr + grp + 8) * QS_PITCH + k0 + tig]);
            a[2] = __float_as_uint(Qs[(wr + grp) * QS_PITCH + k0 + 4 + tig]);
            a[3] = __float_as_uint(Qs[(wr + grp + 8) * QS_PITCH + k0 + 4 + tig]);
            #pragma unroll
            for (int fn = 0; fn < 8; fn++) {
                unsigned bb[2];
                bb[0] = __float_as_uint(ks[(fn * 8 + grp) * QS_PITCH + k0 + tig]);
                bb[1] = __float_as_uint(ks[(fn * 8 + grp) * QS_PITCH + k0 + 4 + tig]);
                MMA_TF32(acc_s[fn], a, bb);
            }
        }
        float mx_lo = -1e30f, mx_hi = -1e30f;
        #pragma unroll
        for (int fn = 0; fn < 8; fn++) {
            int col = fn * 8 + 2 * tig;
            float2 blo = *reinterpret_cast<float2*>(&ms[(wr + grp) * MS_PITCH + col]);
            float2 bhi = *reinterpret_cast<float2*>(&ms[(wr + grp + 8) * MS_PITCH + col]);
            acc_s[fn][0] += BIGF * (blo.x - 1.0f);
            acc_s[fn][1] += BIGF * (blo.y - 1.0f);
            acc_s[fn][2] += BIGF * (bhi.x - 1.0f);
            acc_s[fn][3] += BIGF * (bhi.y - 1.0f);
            mx_lo = fmaxf(mx_lo, fmaxf(acc_s[fn][0], acc_s[fn][1]));
            mx_hi = fmaxf(mx_hi, fmaxf(acc_s[fn][2], acc_s[fn][3]));
        }
        mx_lo = fmaxf(mx_lo, __shfl_xor_sync(0xffffffffu, mx_lo, 1));
        mx_lo = fmaxf(mx_lo, __shfl_xor_sync(0xffffffffu, mx_lo, 2));
        mx_hi = fmaxf(mx_hi, __shfl_xor_sync(0xffffffffu, mx_hi, 1));
        mx_hi = fmaxf(mx_hi, __shfl_xor_sync(0xffffffffu, mx_hi, 2));
        float mn_lo = fmaxf(m_lo, mx_lo), mn_hi = fmaxf(m_hi, mx_hi);
        float sc_lo = __expf(m_lo - mn_lo), sc_hi = __expf(m_hi - mn_hi);
        m_lo = mn_lo; m_hi = mn_hi;
        float rs_lo = 0.0f, rs_hi = 0.0f;
        #pragma unroll
        for (int fn = 0; fn < 8; fn++) {
            int col = fn * 8 + 2 * tig;
            float p0 = __expf(acc_s[fn][0] - mn_lo);
            float p1 = __expf(acc_s[fn][1] - mn_lo);
            float p2 = __expf(acc_s[fn][2] - mn_hi);
            float p3 = __expf(acc_s[fn][3] - mn_hi);
            rs_lo += p0 + p1; rs_hi += p2 + p3;
            *reinterpret_cast<float2*>(&ms[(wr + grp) * MS_PITCH + col]) =
                make_float2(to_tf32(p0), to_tf32(p1));
            *reinterpret_cast<float2*>(&ms[(wr + grp + 8) * MS_PITCH + col]) =
                make_float2(to_tf32(p2), to_tf32(p3));
        }
        rs_lo += __shfl_xor_sync(0xffffffffu, rs_lo, 1);
        rs_lo += __shfl_xor_sync(0xffffffffu, rs_lo, 2);
        rs_hi += __shfl_xor_sync(0xffffffffu, rs_hi, 1);
        rs_hi += __shfl_xor_sync(0xffffffffu, rs_hi, 2);
        l_lo = l_lo * sc_lo + rs_lo;
        l_hi = l_hi * sc_hi + rs_hi;
        #pragma unroll
        for (int fn = 0; fn < 6; fn++) {
            acc_o[fn][0] *= sc_lo; acc_o[fn][1] *= sc_lo;
            acc_o[fn][2] *= sc_hi; acc_o[fn][3] *= sc_hi;
        }
        __syncwarp();
        #pragma unroll
        for (int s = 0; s < 8; s++) {
            int k0 = s * 8;
            unsigned a[4];
            a[0] = __float_as_uint(ms[(wr + grp) * MS_PITCH + k0 + tig]);
            a[1] = __float_as_uint(ms[(wr + grp + 8) * MS_PITCH + k0 + tig]);
            a[2] = __float_as_uint(ms[(wr + grp) * MS_PITCH + k0 + 4 + tig]);
            a[3] = __float_as_uint(ms[(wr + grp + 8) * MS_PITCH + k0 + 4 + tig]);
            #pragma unroll
            for (int fn = 0; fn < 6; fn++) {
                unsigned bb[2];
                bb[0] = __float_as_uint(vs[(k0 + tig) * VS_PITCH + fn * 8 + grp]);
                bb[1] = __float_as_uint(vs[(k0 + 4 + tig) * VS_PITCH + fn * 8 + grp]);
                MMA_TF32(acc_o[fn], a, bb);
            }
        }
        __syncthreads();
        if (ch + 2 < NCH) issue(ch + 2, b);
        CP_COMMIT();
    }

    int row_lo = (rsp * H_HEADS + h) * T_TOK + t0 + wr + grp;
    int row_hi = row_lo + 8;
    #pragma unroll
    for (int fn = 0; fn < 6; fn++) {
        int c = fn * 8 + 2 * tig;
        *reinterpret_cast<float2*>(&po[(size_t)row_lo * KD + c]) =
            make_float2(acc_o[fn][0], acc_o[fn][1]);
        *reinterpret_cast<float2*>(&po[(size_t)row_hi * KD + c]) =
            make_float2(acc_o[fn][2], acc_o[fn][3]);
    }
    if (tig == 0) {
        pm[row_lo] = m_lo; pm[row_hi] = m_hi;
        pl[row_lo] = l_lo; pl[row_hi] = l_hi;
    }
}

// ---------------- combine r-splits, apply gate, write wag fp16 ----------------
__global__ void combine_kernel(const float* __restrict__ po, const float* __restrict__ pm,
                               const float* __restrict__ pl, const float* __restrict__ gate,
                               hf* __restrict__ wag) {
    int idx = blockIdx.x * 256 + threadIdx.x;
    const int TOT = H_HEADS * T_TOK * KD;
    const int HT  = H_HEADS * T_TOK;
    if (idx >= TOT) return;
    int c  = idx % KD;
    int ht = idx / KD;
    int tt = ht % T_TOK, h = ht / T_TOK;
    float mm = -1e30f;
    #pragma unroll
    for (int r = 0; r < RSPLIT; r++) mm = fmaxf(mm, pm[r * HT + ht]);
    float l = 0.0f, o = 0.0f;
    #pragma unroll
    for (int r = 0; r < RSPLIT; r++) {
        float s = __expf(pm[r * HT + ht] - mm);
        l += pl[r * HT + ht] * s;
        o += po[(size_t)r * TOT + idx] * s;
    }
    o /= l;
    float g = gate[(size_t)tt * C_DIM + h * KD + c];
    wag[(size_t)tt * C_DIM + h * KD + c] = __float2half_rn(o * g);
}

// ---------------- host launch ----------------
static void* symv(const void* s) {
    void* p = nullptr;
    cudaGetSymbolAddress(&p, s);
    return p;
}

extern "C" void kernel_launch(void* const* d_in, const int* in_sizes, int n_in,
                              void* d_out, int out_size) {
    const float* original   = (const float*)d_in[0];
    const float* resampled  = (const float*)d_in[1];
    const float* attn_mask  = (const float*)d_in[2];
    const float* qn_scale   = (const float*)d_in[5];
    const float* qn_offset  = (const float*)d_in[6];
    const float* dn_scale   = (const float*)d_in[7];
    const float* dn_offset  = (const float*)d_in[8];
    const float* query_w    = (const float*)d_in[9];
    const float* key_w      = (const float*)d_in[10];
    const float* value_w    = (const float*)d_in[11];
    const float* gating_w   = (const float*)d_in[12];
    const float* gating_b   = (const float*)d_in[13];
    const float* output_w   = (const float*)d_in[14];
    const float* output_b   = (const float*)d_in[15];
    const float* rt_ln_scale  = (const float*)d_in[16];
    const float* rt_ln_offset = (const float*)d_in[17];
    const float* rt_w1 = (const float*)d_in[18];
    const float* rt_b1 = (const float*)d_in[19];
    const float* rt_w2 = (const float*)d_in[20];
    const float* rt_b2 = (const float*)d_in[21];
    const float* ot_ln_scale  = (const float*)d_in[22];
    const float* ot_ln_offset = (const float*)d_in[23];
    const float* ot_w1 = (const float*)d_in[24];
    const float* ot_b1 = (const float*)d_in[25];
    const float* ot_w2 = (const float*)d_in[26];
    const float* ot_b2 = (const float*)d_in[27];

    float* out_res  = (float*)d_out;
    float* out_orig = out_res + (size_t)T_TOK * C_DIM;

    hf*    p_qin  = (hf*)symv(g_qin);
    hf*    p_din  = (hf*)symv(g_din);
    hf*    p_ln4  = (hf*)symv(g_ln4);
    float* p_q    = (float*)symv(g_q);
    float* p_gate = (float*)symv(g_gate);
    float* p_k    = (float*)symv(g_k);
    float* p_v    = (float*)symv(g_v);
    hf*    p_wag  = (hf*)symv(g_wag);
    hf*    p_ln3  = (hf*)symv(g_ln3);
    hf*    p_h1   = (hf*)symv(g_h1);
    hf*    p_h2   = (hf*)symv(g_h2);
    hf*    p_wts  = (hf*)symv(g_wts);
    float* p_po   = (float*)symv(g_po);
    float* p_pm   = (float*)symv(g_pm);
    float* p_pl   = (float*)symv(g_pl);

    const int gemm_smem  = STAGES * 2 * STAGE_BYTES;   // 98304 bytes
    const int flash_smem = FL_TOTAL * 4;
    cudaFuncSetAttribute(gemm_hf, cudaFuncAttributeMaxDynamicSharedMemorySize, gemm_smem);
    cudaFuncSetAttribute(flash_kernel, cudaFuncAttributeMaxDynamicSharedMemorySize, flash_smem);

    const float inv_sqrt_kd = 0.14433756729740643f;
    const int BIG_HALF = 1 << 30;

    cudaStream_t s2 = 0;
    cudaEvent_t ev0 = 0, ev1 = 0;
    cudaStreamCreateWithFlags(&s2, cudaStreamNonBlocking);
    cudaEventCreateWithFlags(&ev0, cudaEventDisableTiming);
    cudaEventCreateWithFlags(&ev1, cudaEventDisableTiming);
    bool fork_ok = (s2 != 0) && (ev0 != 0) && (ev1 != 0);

    // 1) transpose + fp16-convert all weights (one launch)
    SrcPtrs sp;
    sp.p[0] = query_w;  sp.p[1] = key_w;  sp.p[2] = value_w;
    sp.p[3] = gating_w; sp.p[4] = output_w;
    sp.p[5] = rt_w1;    sp.p[6] = rt_w2;  sp.p[7] = ot_w1; sp.p[8] = ot_w2;
    wt_kernel<<<3024, 256>>>(sp, p_wts);

    // 2) fused input LayerNorms (fp16 outputs)
    ln_fused_kernel<<<T_TOK + 2 * N_RES, 128>>>(resampled, original,
        qn_scale, qn_offset, dn_scale, dn_offset, ot_ln_scale, ot_ln_offset,
        p_qin, p_din, p_ln4);

    // 3) fork: original transition on s2
    cudaStream_t br = 0;
    if (fork_ok) {
        cudaEventRecord(ev0, 0);
        cudaStreamWaitEvent(s2, ev0, 0);
        br = s2;
    }
    gemm_hf<<<dim3(12, 32), 256, gemm_smem, br>>>(p_ln4,
        p_wts + OFF_OT1, p_h2, 1.0f, ot_b1, ACT_RELU, nullptr, 2,
        nullptr, nullptr, 0.0f, nullptr, 0, nullptr, 0,
        N_RES, F_DIM, C_DIM, BIG_HALF);
    gemm_hf<<<dim3(3, 32), 256, gemm_smem, br>>>(p_h2,
        p_wts + OFF_OT2, out_orig, 1.0f, ot_b2, ACT_NONE, original, 0,
        nullptr, nullptr, 0.0f, nullptr, 0, nullptr, 0,
        N_RES, C_DIM, F_DIM, BIG_HALF);
    if (fork_ok) cudaEventRecord(ev1, s2);

    // 4) main chain
    gemm_hf<<<dim3(6, 4), 256, gemm_smem>>>(p_qin,
        p_wts + OFF_QW, p_q, inv_sqrt_kd, nullptr, ACT_NONE, nullptr, 1,
        p_wts + OFF_GW, p_gate, 1.0f, gating_b, ACT_SIGMOID, nullptr, 0,
        T_TOK, C_DIM, C_DIM, 3);
    gemm_hf<<<dim3(6, 32), 256, gemm_smem>>>(p_din,
        p_wts + OFF_KW, p_k, 1.0f, nullptr, ACT_NONE, nullptr, 1,
        p_wts + OFF_VW, p_v, 1.0f, nullptr, ACT_NONE, nullptr, 1,
        N_RES, C_DIM, C_DIM, 3);

    flash_kernel<<<dim3(T_TOK / 64, H_HEADS, RSPLIT), 128, flash_smem>>>(
        p_q, p_k, p_v, attn_mask, p_po, p_pm, p_pl);
    combine_kernel<<<(H_HEADS * T_TOK * KD + 255) / 256, 256>>>(p_po, p_pm, p_pl, p_gate, p_wag);

    gemm_hf<<<dim3(3, 4), 256, gemm_smem>>>(p_wag,
        p_wts + OFF_OW, out_res, 1.0f, output_b, ACT_NONE, resampled, 0,
        nullptr, nullptr, 0.0f, nullptr, 0, nullptr, 0,
        T_TOK, C_DIM, C_DIM, BIG_HALF);

    ln_kernel<<<T_TOK, 128>>>(out_res, rt_ln_scale, rt_ln_offset, p_ln3);
    gemm_hf<<<dim3(12, 4), 256, gemm_smem>>>(p_ln3,
        p_wts + OFF_RT1, p_h1, 1.0f, rt_b1, ACT_RELU, nullptr, 2,
        nullptr, nullptr, 0.0f, nullptr, 0, nullptr, 0,
        T_TOK, F_DIM, C_DIM, BIG_HALF);
    gemm_hf<<<dim3(3, 4), 256, gemm_smem>>>(p_h1,
        p_wts + OFF_RT2, out_res, 1.0f, rt_b2, ACT_NONE, out_res, 0,
        nullptr, nullptr, 0.0f, nullptr, 0, nullptr, 0,
        T_TOK, C_DIM, F_DIM, BIG_HALF);

    // 5) join
    if (fork_ok) cudaStreamWaitEvent(0, ev1, 0);
}

// round 8
// speedup vs baseline: 1.4669x; 1.4669x over previous
#include <cuda_runtime.h>
#include <cuda_fp16.h>
#include <math.h>

#define T_TOK 512
#define N_RES 4096
#define C_DIM 384
#define H_HEADS 8
#define KD 48
#define F_DIM 1536
#define LN_EPS 1e-5f
#define BIGF 1e9f
#define RSPLIT 4
#define RCHUNK 64
#define STAGES 3
#define BK 32

typedef __half hf;

// ---------------- scratch (device globals) ----------------
__device__ hf    g_qin [T_TOK * C_DIM];
__device__ hf    g_din [N_RES * C_DIM];
__device__ hf    g_ln4 [N_RES * C_DIM];
__device__ float g_q   [T_TOK * C_DIM];
__device__ float g_gate[T_TOK * C_DIM];
__device__ float g_k   [N_RES * C_DIM];
__device__ float g_v   [N_RES * C_DIM];
__device__ hf    g_wag [T_TOK * C_DIM];
__device__ hf    g_ln3 [T_TOK * C_DIM];
__device__ hf    g_h1  [T_TOK * F_DIM];
__device__ hf    g_h2  [N_RES * F_DIM];
// fp16 TRANSPOSED weights Wt[N][K] (element offsets)
#define OFF_QW  0
#define OFF_KW  147456
#define OFF_VW  294912
#define OFF_GW  442368
#define OFF_OW  589824
#define OFF_RT1 737280
#define OFF_RT2 1327104
#define OFF_OT1 1916928
#define OFF_OT2 2506752
#define WTS_TOTAL 3096576
__device__ hf g_wts[WTS_TOTAL];
// flash partials
__device__ float g_po[RSPLIT * H_HEADS * T_TOK * KD];
__device__ float g_pm[RSPLIT * H_HEADS * T_TOK];
__device__ float g_pl[RSPLIT * H_HEADS * T_TOK];

__device__ __forceinline__ float to_tf32(float x) {
    asm("cvt.rna.tf32.f32 %0, %1;" : "=f"(x) : "f"(x));
    return x;
}

#define MMA_TF32(c, a, b) \
    asm volatile("mma.sync.aligned.m16n8k8.row.col.f32.tf32.tf32.f32 " \
        "{%0,%1,%2,%3}, {%4,%5,%6,%7}, {%8,%9}, {%0,%1,%2,%3};" \
        : "+f"((c)[0]), "+f"((c)[1]), "+f"((c)[2]), "+f"((c)[3]) \
        : "r"((a)[0]), "r"((a)[1]), "r"((a)[2]), "r"((a)[3]), \
          "r"((b)[0]), "r"((b)[1]))

#define MMA_F16(c, a, b) \
    asm volatile("mma.sync.aligned.m16n8k16.row.col.f32.f16.f16.f32 " \
        "{%0,%1,%2,%3}, {%4,%5,%6,%7}, {%8,%9}, {%0,%1,%2,%3};" \
        : "+f"((c)[0]), "+f"((c)[1]), "+f"((c)[2]), "+f"((c)[3]) \
        : "r"((a)[0]), "r"((a)[1]), "r"((a)[2]), "r"((a)[3]), \
          "r"((b)[0]), "r"((b)[1]))

__device__ __forceinline__ void cp16(void* dst, const void* src) {
    unsigned d = (unsigned)__cvta_generic_to_shared(dst);
    asm volatile("cp.async.ca.shared.global [%0], [%1], 16;" :: "r"(d), "l"(src));
}
#define CP_COMMIT() asm volatile("cp.async.commit_group;")
#define CP_WAIT(n)  asm volatile("cp.async.wait_group %0;" :: "n"(n))

// ---------------- weight transpose + fp16 convert: W[K][N] fp32 -> Wt[N][K] fp16 ----------------
struct SrcPtrs { const float* p[9]; };

__global__ __launch_bounds__(256) void wt_kernel(SrcPtrs s, hf* __restrict__ dst) {
    const int segK[9]   = {384, 384, 384, 384, 384, 384, 1536, 384, 1536};
    const int segN[9]   = {384, 384, 384, 384, 384, 1536, 384, 1536, 384};
    const int segOff[9] = {OFF_QW, OFF_KW, OFF_VW, OFF_GW, OFF_OW, OFF_RT1, OFF_RT2, OFF_OT1, OFF_OT2};
    const int cum[10]   = {0, 144, 288, 432, 576, 720, 1296, 1872, 2448, 3024};
    int b = blockIdx.x;
    int seg = 0;
    #pragma unroll
    for (int i = 1; i < 9; i++) if (b >= cum[i]) seg = i;
    int tile = b - cum[seg];
    int K = segK[seg], N = segN[seg];
    int ntn = N >> 5;
    int k0 = (tile / ntn) * 32, n0 = (tile % ntn) * 32;
    const float* src = s.p[seg];

    __shared__ float smt[32][33];
    int t = threadIdx.x;
    int r = t >> 3, c4 = (t & 7) * 4;
    float4 v = *reinterpret_cast<const float4*>(&src[(size_t)(k0 + r) * N + n0 + c4]);
    smt[r][c4 + 0] = v.x; smt[r][c4 + 1] = v.y;
    smt[r][c4 + 2] = v.z; smt[r][c4 + 3] = v.w;
    __syncthreads();
    int n = t >> 3, k4 = (t & 7) * 4;
    __half2 lo = __floats2half2_rn(smt[k4 + 0][n], smt[k4 + 1][n]);
    __half2 hi = __floats2half2_rn(smt[k4 + 2][n], smt[k4 + 3][n]);
    hf* d = dst + segOff[seg] + (size_t)(n0 + n) * K + k0 + k4;
    *reinterpret_cast<__half2*>(d)     = lo;
    *reinterpret_cast<__half2*>(d + 2) = hi;
}

// ---------------- LayerNorm core ----------------
__device__ __forceinline__ void ln_row(const float* __restrict__ xr,
                                       const float* __restrict__ scale,
                                       const float* __restrict__ offset,
                                       hf* __restrict__ orow) {
    int t = threadIdx.x;
    float v0 = xr[t], v1 = xr[t + 128], v2 = xr[t + 256];
    float s  = v0 + v1 + v2;
    float s2 = v0 * v0 + v1 * v1 + v2 * v2;
    #pragma unroll
    for (int o = 16; o; o >>= 1) {
        s  += __shfl_down_sync(0xffffffffu, s,  o);
        s2 += __shfl_down_sync(0xffffffffu, s2, o);
    }
    __shared__ float sh[8];
    __shared__ float mu_s, rstd_s;
    int wid = t >> 5, lane = t & 31;
    if (lane == 0) { sh[wid] = s; sh[4 + wid] = s2; }
    __syncthreads();
    if (t == 0) {
        float ts  = sh[0] + sh[1] + sh[2] + sh[3];
        float ts2 = sh[4] + sh[5] + sh[6] + sh[7];
        float mu  = ts * (1.0f / C_DIM);
        float var = ts2 * (1.0f / C_DIM) - mu * mu;
        mu_s = mu; rstd_s = rsqrtf(var + LN_EPS);
    }
    __syncthreads();
    float mu = mu_s, rstd = rstd_s;
    orow[t]       = __float2half_rn(scale[t]       * (v0 - mu) * rstd + offset[t]);
    orow[t + 128] = __float2half_rn(scale[t + 128] * (v1 - mu) * rstd + offset[t + 128]);
    orow[t + 256] = __float2half_rn(scale[t + 256] * (v2 - mu) * rstd + offset[t + 256]);
}

__global__ void ln_kernel(const float* __restrict__ x, const float* __restrict__ scale,
                          const float* __restrict__ offset, hf* __restrict__ out) {
    int row = blockIdx.x;
    ln_row(x + (size_t)row * C_DIM, scale, offset, out + (size_t)row * C_DIM);
}

__global__ void ln_fused_kernel(const float* __restrict__ resampled, const float* __restrict__ original,
                                const float* __restrict__ qn_s, const float* __restrict__ qn_o,
                                const float* __restrict__ dn_s, const float* __restrict__ dn_o,
                                const float* __restrict__ ot_s, const float* __restrict__ ot_o,
                                hf* __restrict__ qin, hf* __restrict__ din, hf* __restrict__ ln4) {
    int row = blockIdx.x;
    if (row < T_TOK) {
        ln_row(resampled + (size_t)row * C_DIM, qn_s, qn_o, qin + (size_t)row * C_DIM);
    } else if (row < T_TOK + N_RES) {
        int r = row - T_TOK;
        ln_row(original + (size_t)r * C_DIM, dn_s, dn_o, din + (size_t)r * C_DIM);
    } else {
        int r = row - T_TOK - N_RES;
        ln_row(original + (size_t)r * C_DIM, ot_s, ot_o, ln4 + (size_t)r * C_DIM);
    }
}

// ---------------- MTx128xBK fp16 GEMM, 3-stage cp.async, m16n8k16 ----------------
// A[M][K] fp16, B = Wt[N][K] fp16. modes: 0=f32(+res), 1=f32 tf32-rounded(+res), 2=fp16
#define ACT_NONE 0
#define ACT_RELU 1
#define ACT_SIGMOID 2

template<int MT>
__global__ __launch_bounds__(256, 2) void gemm_hf(
    const hf* __restrict__ A,
    const hf* __restrict__ B0, void* __restrict__ C0v, float alpha0,
    const float* __restrict__ bias0, int act0, const float* __restrict__ res0, int mode0,
    const hf* __restrict__ B1, void* __restrict__ C1v, float alpha1,
    const float* __restrict__ bias1, int act1, const float* __restrict__ res1, int mode1,
    int M, int N, int K, int halfX) {
    constexpr int A_STAGE = MT * BK;       // halves per A stage
    constexpr int B_STAGE = 128 * BK;
    constexpr int FM = MT / 32;            // m-frags per warp (4 or 2)
    constexpr int AG = MT / 64;            // A granules per thread (2 or 1)
    extern __shared__ hf smg[];
    hf* As = smg;
    hf* Bs = smg + STAGES * A_STAGE;

    int t = threadIdx.x;
    int bxx = blockIdx.x;
    const hf* B = B0; void* Cv = C0v; float alpha = alpha0;
    const float* bias = bias0; int act = act0; const float* residual = res0; int mode = mode0;
    if (bxx >= halfX) {
        bxx -= halfX;
        B = B1; Cv = C1v; alpha = alpha1; bias = bias1; act = act1; residual = res1; mode = mode1;
    }
    int bm = blockIdx.y * MT, bn = bxx * 128;
    int wid = t >> 5, lane = t & 31, grp = lane >> 2, tig = lane & 3;
    int wm = (wid >> 2) * (MT / 2);
    int wn = (wid & 3) * 32;

    // cp.async mapping: granule = 8 halves; swizzle g ^ ((row>>1)&3)
    int a_dst[AG]; size_t a_src[AG];
    #pragma unroll
    for (int i = 0; i < AG; i++) {
        int idx = t + i * 256;
        int m = idx >> 2, g = idx & 3;
        a_dst[i] = (m * 4 + (g ^ ((m >> 1) & 3))) * 8;
        a_src[i] = (size_t)(bm + m) * K + g * 8;
    }
    int b_dst[2]; size_t b_src[2];
    #pragma unroll
    for (int i = 0; i < 2; i++) {
        int idx = t + i * 256;
        int n = idx >> 2, g = idx & 3;
        b_dst[i] = (n * 4 + (g ^ ((n >> 1) & 3))) * 8;
        b_src[i] = (size_t)(bn + n) * K + g * 8;
    }

    float acc[FM][4][4];
    #pragma unroll
    for (int i = 0; i < FM; i++)
        #pragma unroll
        for (int j = 0; j < 4; j++)
            #pragma unroll
            for (int r = 0; r < 4; r++) acc[i][j][r] = 0.0f;

    int kTiles = K / BK;

    #pragma unroll
    for (int pt = 0; pt < STAGES - 1; pt++) {
        hf* ab = As + pt * A_STAGE;
        hf* bb = Bs + pt * B_STAGE;
        #pragma unroll
        for (int i = 0; i < AG; i++) cp16(ab + a_dst[i], A + a_src[i] + pt * BK);
        #pragma unroll
        for (int i = 0; i < 2; i++)  cp16(bb + b_dst[i], B + b_src[i] + pt * BK);
        CP_COMMIT();
    }

    for (int kt = 0; kt < kTiles; kt++) {
        CP_WAIT(STAGES - 2);
        __syncthreads();
        int nt = kt + STAGES - 1;
        if (nt < kTiles) {
            int buf = nt % STAGES;
            hf* ab = As + buf * A_STAGE;
            hf* bb = Bs + buf * B_STAGE;
            #pragma unroll
            for (int i = 0; i < AG; i++) cp16(ab + a_dst[i], A + a_src[i] + nt * BK);
            #pragma unroll
            for (int i = 0; i < 2; i++)  cp16(bb + b_dst[i], B + b_src[i] + nt * BK);
        }
        CP_COMMIT();
        const hf* as = As + (kt % STAGES) * A_STAGE;
        const hf* bs = Bs + (kt % STAGES) * B_STAGE;
        #pragma unroll
        for (int s = 0; s < 2; s++) {           // 2 x k16 steps
            unsigned af[FM][4];
            #pragma unroll
            for (int fm = 0; fm < FM; fm++) {
                int m = wm + fm * 16 + grp;
                int sw = (m >> 1) & 3;
                int g0 = (2 * s) ^ sw, g1 = (2 * s + 1) ^ sw;
                af[fm][0] = *reinterpret_cast<const unsigned*>(as + m * BK + g0 * 8 + tig * 2);
                af[fm][1] = *reinterpret_cast<const unsigned*>(as + (m + 8) * BK + g0 * 8 + tig * 2);
                af[fm][2] = *reinterpret_cast<const unsigned*>(as + m * BK + g1 * 8 + tig * 2);
                af[fm][3] = *reinterpret_cast<const unsigned*>(as + (m + 8) * BK + g1 * 8 + tig * 2);
            }
            unsigned bfr[4][2];
            #pragma unroll
            for (int fn = 0; fn < 4; fn++) {
                int n = wn + fn * 8 + grp;
                int sw = (n >> 1) & 3;
                int g0 = (2 * s) ^ sw, g1 = (2 * s + 1) ^ sw;
                bfr[fn][0] = *reinterpret_cast<const unsigned*>(bs + n * BK + g0 * 8 + tig * 2);
                bfr[fn][1] = *reinterpret_cast<const unsigned*>(bs + n * BK + g1 * 8 + tig * 2);
            }
            #pragma unroll
            for (int fm = 0; fm < FM; fm++)
                #pragma unroll
                for (int fn = 0; fn < 4; fn++)
                    MMA_F16(acc[fm][fn], af[fm], bfr[fn]);
        }
        __syncthreads();
    }

    #pragma unroll
    for (int fm = 0; fm < FM; fm++) {
        #pragma unroll
        for (int fn = 0; fn < 4; fn++) {
            int m0 = bm + wm + fm * 16 + grp;
            int n  = bn + wn + fn * 8 + tig * 2;
            #pragma unroll
            for (int half = 0; half < 2; half++) {
                int m = m0 + half * 8;
                float x0 = acc[fm][fn][half * 2 + 0] * alpha;
                float x1 = acc[fm][fn][half * 2 + 1] * alpha;
                if (bias) { x0 += bias[n]; x1 += bias[n + 1]; }
                if (act == ACT_RELU) {
                    x0 = fmaxf(x0, 0.0f); x1 = fmaxf(x1, 0.0f);
                } else if (act == ACT_SIGMOID) {
                    x0 = 1.0f / (1.0f + __expf(-x0));
                    x1 = 1.0f / (1.0f + __expf(-x1));
                }
                if (mode == 2) {
                    hf* Cb = (hf*)Cv;
                    *reinterpret_cast<__half2*>(&Cb[(size_t)m * N + n]) =
                        __floats2half2_rn(x0, x1);
                } else {
                    float* Cf = (float*)Cv;
                    if (residual) {
                        float2 r = *reinterpret_cast<const float2*>(&residual[(size_t)m * N + n]);
                        x0 += r.x; x1 += r.y;
                    }
                    if (mode == 1) { x0 = to_tf32(x0); x1 = to_tf32(x1); }
                    *reinterpret_cast<float2*>(&Cf[(size_t)m * N + n]) = make_float2(x0, x1);
                }
            }
        }
    }
}

// ---------------- flash attention (tf32, unchanged) ----------------
#define QS_PITCH 52
#define VS_PITCH 56
#define MS_PITCH 68
#define FL_QS 0
#define FL_KS (64*52)
#define FL_VS (FL_KS + 2*64*52)
#define FL_MS (FL_VS + 2*64*56)
#define FL_TOTAL (FL_MS + 2*64*68)

__global__ __launch_bounds__(128) void flash_kernel(
    const float* __restrict__ q, const float* __restrict__ k,
    const float* __restrict__ v, const float* __restrict__ mask,
    float* __restrict__ po, float* __restrict__ pm, float* __restrict__ pl) {
    extern __shared__ float sm[];
    float* Qs = sm + FL_QS;
    int t = threadIdx.x;
    int wid = t >> 5, lane = t & 31, grp = lane >> 2, tig = lane & 3;
    int t0 = blockIdx.x * 64;
    int h  = blockIdx.y;
    int rsp = blockIdx.z;
    int rbase = rsp * (N_RES / RSPLIT);
    int wr = wid * 16;

    for (int i = t; i < 64 * 12; i += 128) {
        int r = i / 12, f = i % 12;
        float4 q4 = *reinterpret_cast<const float4*>(&q[(size_t)(t0 + r) * C_DIM + h * KD + f * 4]);
        *reinterpret_cast<float4*>(&Qs[r * QS_PITCH + f * 4]) = q4;
    }

    const int NCH = (N_RES / RSPLIT) / RCHUNK;   // 16

    auto issue = [&](int ch, int b) {
        int r0 = rbase + ch * RCHUNK;
        float* ks = sm + FL_KS + b * 64 * QS_PITCH;
        float* vs = sm + FL_VS + b * 64 * VS_PITCH;
        float* ms = sm + FL_MS + b * 64 * MS_PITCH;
        for (int i = t; i < 64 * 12; i += 128) {
            int r = i / 12, f = i % 12;
            size_t src = (size_t)(r0 + r) * C_DIM + h * KD + f * 4;
            cp16(&ks[r * QS_PITCH + f * 4], &k[src]);
            cp16(&vs[r * VS_PITCH + f * 4], &v[src]);
        }
        for (int i = t; i < 64 * 16; i += 128) {
            int rr = i / 16, f = i % 16;
            cp16(&ms[rr * MS_PITCH + f * 4],
                 &mask[((size_t)h * T_TOK + t0 + rr) * N_RES + r0 + f * 4]);
        }
    };

    issue(0, 0); CP_COMMIT();
    issue(1, 1); CP_COMMIT();

    float m_lo = -1e30f, m_hi = -1e30f, l_lo = 0.0f, l_hi = 0.0f;
    float acc_o[6][4];
    #pragma unroll
    for (int i = 0; i < 6; i++)
        #pragma unroll
        for (int e = 0; e < 4; e++) acc_o[i][e] = 0.0f;

    for (int ch = 0; ch < NCH; ch++) {
        int b = ch & 1;
        CP_WAIT(1);
        __syncthreads();
        float* ks = sm + FL_KS + b * 64 * QS_PITCH;
        float* vs = sm + FL_VS + b * 64 * VS_PITCH;
        float* ms = sm + FL_MS + b * 64 * MS_PITCH;

        float acc_s[8][4];
        #pragma unroll
        for (int fn = 0; fn < 8; fn++)
            #pragma unroll
            for (int e = 0; e < 4; e++) acc_s[fn][e] = 0.0f;
        #pragma unroll
        for (int s = 0; s < 6; s++) {
            int k0 = s * 8;
            unsigned a[4];
            a[0] = __float_as_uint(Qs[(wr + grp) * QS_PITCH + k0 + tig]);
            a[1] = __float_as_uint(Qs[(wr + grp + 8) * QS_PITCH + k0 + tig]);
            a[2] = __float_as_uint(Qs[(wr + grp) * QS_PITCH + k0 + 4 + tig]);
            a[3] = __float_as_uint(Qs[(wr + grp + 8) * QS_PITCH + k0 + 4 + tig]);
            #pragma unroll
            for (int fn = 0; fn < 8; fn++) {
                unsigned bb[2];
                bb[0] = __float_as_uint(ks[(fn * 8 + grp) * QS_PITCH + k0 + tig]);
                bb[1] = __float_as_uint(ks[(fn * 8 + grp) * QS_PITCH + k0 + 4 + tig]);
                MMA_TF32(acc_s[fn], a, bb);
            }
        }
        float mx_lo = -1e30f, mx_hi = -1e30f;
        #pragma unroll
        for (int fn = 0; fn < 8; fn++) {
            int col = fn * 8 + 2 * tig;
            float2 blo = *reinterpret_cast<float2*>(&ms[(wr + grp) * MS_PITCH + col]);
            float2 bhi = *reinterpret_cast<float2*>(&ms[(wr + grp + 8) * MS_PITCH + col]);
            acc_s[fn][0] += BIGF * (blo.x - 1.0f);
            acc_s[fn][1] += BIGF * (blo.y - 1.0f);
            acc_s[fn][2] += BIGF * (bhi.x - 1.0f);
            acc_s[fn][3] += BIGF * (bhi.y - 1.0f);
            mx_lo = fmaxf(mx_lo, fmaxf(acc_s[fn][0], acc_s[fn][1]));
            mx_hi = fmaxf(mx_hi, fmaxf(acc_s[fn][2], acc_s[fn][3]));
        }
        mx_lo = fmaxf(mx_lo, __shfl_xor_sync(0xffffffffu, mx_lo, 1));
        mx_lo = fmaxf(mx_lo, __shfl_xor_sync(0xffffffffu, mx_lo, 2));
        mx_hi = fmaxf(mx_hi, __shfl_xor_sync(0xffffffffu, mx_hi, 1));
        mx_hi = fmaxf(mx_hi, __shfl_xor_sync(0xffffffffu, mx_hi, 2));
        float mn_lo = fmaxf(m_lo, mx_lo), mn_hi = fmaxf(m_hi, mx_hi);
        float sc_lo = __expf(m_lo - mn_lo), sc_hi = __expf(m_hi - mn_hi);
        m_lo = mn_lo; m_hi = mn_hi;
        float rs_lo = 0.0f, rs_hi = 0.0f;
        #pragma unroll
        for (int fn = 0; fn < 8; fn++) {
            int col = fn * 8 + 2 * tig;
            float p0 = __expf(acc_s[fn][0] - mn_lo);
            float p1 = __expf(acc_s[fn][1] - mn_lo);
            float p2 = __expf(acc_s[fn][2] - mn_hi);
            float p3 = __expf(acc_s[fn][3] - mn_hi);
            rs_lo += p0 + p1; rs_hi += p2 + p3;
            *reinterpret_cast<float2*>(&ms[(wr + grp) * MS_PITCH + col]) =
                make_float2(to_tf32(p0), to_tf32(p1));
            *reinterpret_cast<float2*>(&ms[(wr + grp + 8) * MS_PITCH + col]) =
                make_float2(to_tf32(p2), to_tf32(p3));
        }
        rs_lo += __shfl_xor_sync(0xffffffffu, rs_lo, 1);
        rs_lo += __shfl_xor_sync(0xffffffffu, rs_lo, 2);
        rs_hi += __shfl_xor_sync(0xffffffffu, rs_hi, 1);
        rs_hi += __shfl_xor_sync(0xffffffffu, rs_hi, 2);
        l_lo = l_lo * sc_lo + rs_lo;
        l_hi = l_hi * sc_hi + rs_hi;
        #pragma unroll
        for (int fn = 0; fn < 6; fn++) {
            acc_o[fn][0] *= sc_lo; acc_o[fn][1] *= sc_lo;
            acc_o[fn][2] *= sc_hi; acc_o[fn][3] *= sc_hi;
        }
        __syncwarp();
        #pragma unroll
        for (int s = 0; s < 8; s++) {
            int k0 = s * 8;
            unsigned a[4];
            a[0] = __float_as_uint(ms[(wr + grp) * MS_PITCH + k0 + tig]);
            a[1] = __float_as_uint(ms[(wr + grp + 8) * MS_PITCH + k0 + tig]);
            a[2] = __float_as_uint(ms[(wr + grp) * MS_PITCH + k0 + 4 + tig]);
            a[3] = __float_as_uint(ms[(wr + grp + 8) * MS_PITCH + k0 + 4 + tig]);
            #pragma unroll
            for (int fn = 0; fn < 6; fn++) {
                unsigned bb[2];
                bb[0] = __float_as_uint(vs[(k0 + tig) * VS_PITCH + fn * 8 + grp]);
                bb[1] = __float_as_uint(vs[(k0 + 4 + tig) * VS_PITCH + fn * 8 + grp]);
                MMA_TF32(acc_o[fn], a, bb);
            }
        }
        __syncthreads();
        if (ch + 2 < NCH) issue(ch + 2, b);
        CP_COMMIT();
    }

    int row_lo = (rsp * H_HEADS + h) * T_TOK + t0 + wr + grp;
    int row_hi = row_lo + 8;
    #pragma unroll
    for (int fn = 0; fn < 6; fn++) {
        int c = fn * 8 + 2 * tig;
        *reinterpret_cast<float2*>(&po[(size_t)row_lo * KD + c]) =
            make_float2(acc_o[fn][0], acc_o[fn][1]);
        *reinterpret_cast<float2*>(&po[(size_t)row_hi * KD + c]) =
            make_float2(acc_o[fn][2], acc_o[fn][3]);
    }
    if (tig == 0) {
        pm[row_lo] = m_lo; pm[row_hi] = m_hi;
        pl[row_lo] = l_lo; pl[row_hi] = l_hi;
    }
}

// ---------------- combine r-splits, apply gate, write wag fp16 ----------------
__global__ void combine_kernel(const float* __restrict__ po, const float* __restrict__ pm,
                               const float* __restrict__ pl, const float* __restrict__ gate,
                               hf* __restrict__ wag) {
    int idx = blockIdx.x * 256 + threadIdx.x;
    const int TOT = H_HEADS * T_TOK * KD;
    const int HT  = H_HEADS * T_TOK;
    if (idx >= TOT) return;
    int c  = idx % KD;
    int ht = idx / KD;
    int tt = ht % T_TOK, h = ht / T_TOK;
    float mm = -1e30f;
    #pragma unroll
    for (int r = 0; r < RSPLIT; r++) mm = fmaxf(mm, pm[r * HT + ht]);
    float l = 0.0f, o = 0.0f;
    #pragma unroll
    for (int r = 0; r < RSPLIT; r++) {
        float s = __expf(pm[r * HT + ht] - mm);
        l += pl[r * HT + ht] * s;
        o += po[(size_t)r * TOT + idx] * s;
    }
    o /= l;
    float g = gate[(size_t)tt * C_DIM + h * KD + c];
    wag[(size_t)tt * C_DIM + h * KD + c] = __float2half_rn(o * g);
}

// ---------------- host launch ----------------
static void* symv(const void* s) {
    void* p = nullptr;
    cudaGetSymbolAddress(&p, s);
    return p;
}

extern "C" void kernel_launch(void* const* d_in, const int* in_sizes, int n_in,
                              void* d_out, int out_size) {
    const float* original   = (const float*)d_in[0];
    const float* resampled  = (const float*)d_in[1];
    const float* attn_mask  = (const float*)d_in[2];
    const float* qn_scale   = (const float*)d_in[5];
    const float* qn_offset  = (const float*)d_in[6];
    const float* dn_scale   = (const float*)d_in[7];
    const float* dn_offset  = (const float*)d_in[8];
    const float* query_w    = (const float*)d_in[9];
    const float* key_w      = (const float*)d_in[10];
    const float* value_w    = (const float*)d_in[11];
    const float* gating_w   = (const float*)d_in[12];
    const float* gating_b   = (const float*)d_in[13];
    const float* output_w   = (const float*)d_in[14];
    const float* output_b   = (const float*)d_in[15];
    const float* rt_ln_scale  = (const float*)d_in[16];
    const float* rt_ln_offset = (const float*)d_in[17];
    const float* rt_w1 = (const float*)d_in[18];
    const float* rt_b1 = (const float*)d_in[19];
    const float* rt_w2 = (const float*)d_in[20];
    const float* rt_b2 = (const float*)d_in[21];
    const float* ot_ln_scale  = (const float*)d_in[22];
    const float* ot_ln_offset = (const float*)d_in[23];
    const float* ot_w1 = (const float*)d_in[24];
    const float* ot_b1 = (const float*)d_in[25];
    const float* ot_w2 = (const float*)d_in[26];
    const float* ot_b2 = (const float*)d_in[27];

    float* out_res  = (float*)d_out;
    float* out_orig = out_res + (size_t)T_TOK * C_DIM;

    hf*    p_qin  = (hf*)symv(g_qin);
    hf*    p_din  = (hf*)symv(g_din);
    hf*    p_ln4  = (hf*)symv(g_ln4);
    float* p_q    = (float*)symv(g_q);
    float* p_gate = (float*)symv(g_gate);
    float* p_k    = (float*)symv(g_k);
    float* p_v    = (float*)symv(g_v);
    hf*    p_wag  = (hf*)symv(g_wag);
    hf*    p_ln3  = (hf*)symv(g_ln3);
    hf*    p_h1   = (hf*)symv(g_h1);
    hf*    p_h2   = (hf*)symv(g_h2);
    hf*    p_wts  = (hf*)symv(g_wts);
    float* p_po   = (float*)symv(g_po);
    float* p_pm   = (float*)symv(g_pm);
    float* p_pl   = (float*)symv(g_pl);

    const int smem128 = STAGES * (128 * BK + 128 * BK) * 2;   // 49152 B
    const int smem64  = STAGES * (64 * BK + 128 * BK) * 2;    // 36864 B
    const int flash_smem = FL_TOTAL * 4;
    cudaFuncSetAttribute(gemm_hf<128>, cudaFuncAttributeMaxDynamicSharedMemorySize, smem128);
    cudaFuncSetAttribute(gemm_hf<64>,  cudaFuncAttributeMaxDynamicSharedMemorySize, smem64);
    cudaFuncSetAttribute(flash_kernel, cudaFuncAttributeMaxDynamicSharedMemorySize, flash_smem);

    const float inv_sqrt_kd = 0.14433756729740643f;
    const int BIG_HALF = 1 << 30;

    cudaStream_t s2 = 0;
    cudaEvent_t ev0 = 0, ev1 = 0;
    cudaStreamCreateWithFlags(&s2, cudaStreamNonBlocking);
    cudaEventCreateWithFlags(&ev0, cudaEventDisableTiming);
    cudaEventCreateWithFlags(&ev1, cudaEventDisableTiming);
    bool fork_ok = (s2 != 0) && (ev0 != 0) && (ev1 != 0);

    // 1) transpose + fp16-convert all weights (one launch)
    SrcPtrs sp;
    sp.p[0] = query_w;  sp.p[1] = key_w;  sp.p[2] = value_w;
    sp.p[3] = gating_w; sp.p[4] = output_w;
    sp.p[5] = rt_w1;    sp.p[6] = rt_w2;  sp.p[7] = ot_w1; sp.p[8] = ot_w2;
    wt_kernel<<<3024, 256>>>(sp, p_wts);

    // 2) fused input LayerNorms (fp16 outputs)
    ln_fused_kernel<<<T_TOK + 2 * N_RES, 128>>>(resampled, original,
        qn_scale, qn_offset, dn_scale, dn_offset, ot_ln_scale, ot_ln_offset,
        p_qin, p_din, p_ln4);

    // 3) fork: original transition on s2
    cudaStream_t br = 0;
    if (fork_ok) {
        cudaEventRecord(ev0, 0);
        cudaStreamWaitEvent(s2, ev0, 0);
        br = s2;
    }
    gemm_hf<128><<<dim3(12, 32), 256, smem128, br>>>(p_ln4,
        p_wts + OFF_OT1, p_h2, 1.0f, ot_b1, ACT_RELU, nullptr, 2,
        nullptr, nullptr, 0.0f, nullptr, 0, nullptr, 0,
        N_RES, F_DIM, C_DIM, BIG_HALF);
    gemm_hf<64><<<dim3(3, 64), 256, smem64, br>>>(p_h2,
        p_wts + OFF_OT2, out_orig, 1.0f, ot_b2, ACT_NONE, original, 0,
        nullptr, nullptr, 0.0f, nullptr, 0, nullptr, 0,
        N_RES, C_DIM, F_DIM, BIG_HALF);
    if (fork_ok) cudaEventRecord(ev1, s2);

    // 4) main chain
    gemm_hf<64><<<dim3(6, 8), 256, smem64>>>(p_qin,
        p_wts + OFF_QW, p_q, inv_sqrt_kd, nullptr, ACT_NONE, nullptr, 1,
        p_wts + OFF_GW, p_gate, 1.0f, gating_b, ACT_SIGMOID, nullptr, 0,
        T_TOK, C_DIM, C_DIM, 3);
    gemm_hf<128><<<dim3(6, 32), 256, smem128>>>(p_din,
        p_wts + OFF_KW, p_k, 1.0f, nullptr, ACT_NONE, nullptr, 1,
        p_wts + OFF_VW, p_v, 1.0f, nullptr, ACT_NONE, nullptr, 1,
        N_RES, C_DIM, C_DIM, 3);

    flash_kernel<<<dim3(T_TOK / 64, H_HEADS, RSPLIT), 128, flash_smem>>>(
        p_q, p_k, p_v, attn_mask, p_po, p_pm, p_pl);
    combine_kernel<<<(H_HEADS * T_TOK * KD + 255) / 256, 256>>>(p_po, p_pm, p_pl, p_gate, p_wag);

    gemm_hf<64><<<dim3(3, 8), 256, smem64>>>(p_wag,
        p_wts + OFF_OW, out_res, 1.0f, output_b, ACT_NONE, resampled, 0,
        nullptr, nullptr, 0.0f, nullptr, 0, nullptr, 0,
        T_TOK, C_DIM, C_DIM, BIG_HALF);

    ln_kernel<<<T_TOK, 128>>>(out_res, rt_ln_scale, rt_ln_offset, p_ln3);
    gemm_hf<64><<<dim3(12, 8), 256, smem64>>>(p_ln3,
        p_wts + OFF_RT1, p_h1, 1.0f, rt_b1, ACT_RELU, nullptr, 2,
        nullptr, nullptr, 0.0f, nullptr, 0, nullptr, 0,
        T_TOK, F_DIM, C_DIM, BIG_HALF);
    gemm_hf<64><<<dim3(3, 8), 256, smem64>>>(p_h1,
        p_wts + OFF_RT2, out_res, 1.0f, rt_b2, ACT_NONE, out_res, 0,
        nullptr, nullptr, 0.0f, nullptr, 0, nullptr, 0,
        T_TOK, C_DIM, F_DIM, BIG_HALF);

    // 5) join
    if (fork_ok) cudaStreamWaitEvent(0, ev1, 0);
}

// round 14
// speedup vs baseline: 1.5051x; 1.0261x over previous
#include <cuda_runtime.h>
#include <cuda_fp16.h>
#include <math.h>

#define T_TOK 512
#define N_RES 4096
#define C_DIM 384
#define H_HEADS 8
#define KD 48
#define F_DIM 1536
#define LN_EPS 1e-5f
#define BIGF 1e9f
#define RSPLIT 4
#define RCHUNK 64
#define STAGES 4
#define BK 32

typedef __half hf;

// ---------------- scratch (device globals) ----------------
__device__ hf    g_qin [T_TOK * C_DIM];
__device__ hf    g_din [N_RES * C_DIM];
__device__ hf    g_ln4 [N_RES * C_DIM];
__device__ float g_q   [T_TOK * C_DIM];
__device__ float g_gate[T_TOK * C_DIM];
__device__ float g_k   [N_RES * C_DIM];
__device__ float g_v   [N_RES * C_DIM];
__device__ hf    g_wag [T_TOK * C_DIM];
__device__ hf    g_ln3 [T_TOK * C_DIM];
__device__ hf    g_h1  [T_TOK * F_DIM];
__device__ hf    g_h2  [N_RES * F_DIM];
// fp16 TRANSPOSED weights Wt[N][K] (element offsets)
#define OFF_QW  0
#define OFF_KW  147456
#define OFF_VW  294912
#define OFF_GW  442368
#define OFF_OW  589824
#define OFF_RT1 737280
#define OFF_RT2 1327104
#define OFF_OT1 1916928
#define OFF_OT2 2506752
#define WTS_TOTAL 3096576
__device__ hf g_wts[WTS_TOTAL];
// flash partials
__device__ float g_po[RSPLIT * H_HEADS * T_TOK * KD];
__device__ float g_pm[RSPLIT * H_HEADS * T_TOK];
__device__ float g_pl[RSPLIT * H_HEADS * T_TOK];

__device__ __forceinline__ float to_tf32(float x) {
    asm("cvt.rna.tf32.f32 %0, %1;" : "=f"(x) : "f"(x));
    return x;
}

#define MMA_TF32(c, a, b) \
    asm volatile("mma.sync.aligned.m16n8k8.row.col.f32.tf32.tf32.f32 " \
        "{%0,%1,%2,%3}, {%4,%5,%6,%7}, {%8,%9}, {%0,%1,%2,%3};" \
        : "+f"((c)[0]), "+f"((c)[1]), "+f"((c)[2]), "+f"((c)[3]) \
        : "r"((a)[0]), "r"((a)[1]), "r"((a)[2]), "r"((a)[3]), \
          "r"((b)[0]), "r"((b)[1]))

#define MMA_F16(c, a, b) \
    asm volatile("mma.sync.aligned.m16n8k16.row.col.f32.f16.f16.f32 " \
        "{%0,%1,%2,%3}, {%4,%5,%6,%7}, {%8,%9}, {%0,%1,%2,%3};" \
        : "+f"((c)[0]), "+f"((c)[1]), "+f"((c)[2]), "+f"((c)[3]) \
        : "r"((a)[0]), "r"((a)[1]), "r"((a)[2]), "r"((a)[3]), \
          "r"((b)[0]), "r"((b)[1]))

__device__ __forceinline__ void cp16(void* dst, const void* src) {
    unsigned d = (unsigned)__cvta_generic_to_shared(dst);
    asm volatile("cp.async.ca.shared.global [%0], [%1], 16;" :: "r"(d), "l"(src));
}
#define CP_COMMIT() asm volatile("cp.async.commit_group;")
#define CP_WAIT(n)  asm volatile("cp.async.wait_group %0;" :: "n"(n))

// ---------------- weight transpose + fp16 convert: W[K][N] fp32 -> Wt[N][K] fp16 ----------------
struct SrcPtrs { const float* p[9]; };

__global__ __launch_bounds__(256) void wt_kernel(SrcPtrs s, hf* __restrict__ dst) {
    const int segK[9]   = {384, 384, 384, 384, 384, 384, 1536, 384, 1536};
    const int segN[9]   = {384, 384, 384, 384, 384, 1536, 384, 1536, 384};
    const int segOff[9] = {OFF_QW, OFF_KW, OFF_VW, OFF_GW, OFF_OW, OFF_RT1, OFF_RT2, OFF_OT1, OFF_OT2};
    const int cum[10]   = {0, 144, 288, 432, 576, 720, 1296, 1872, 2448, 3024};
    int b = blockIdx.x;
    int seg = 0;
    #pragma unroll
    for (int i = 1; i < 9; i++) if (b >= cum[i]) seg = i;
    int tile = b - cum[seg];
    int K = segK[seg], N = segN[seg];
    int ntn = N >> 5;
    int k0 = (tile / ntn) * 32, n0 = (tile % ntn) * 32;
    const float* src = s.p[seg];

    __shared__ float smt[32][33];
    int t = threadIdx.x;
    int r = t >> 3, c4 = (t & 7) * 4;
    float4 v = *reinterpret_cast<const float4*>(&src[(size_t)(k0 + r) * N + n0 + c4]);
    smt[r][c4 + 0] = v.x; smt[r][c4 + 1] = v.y;
    smt[r][c4 + 2] = v.z; smt[r][c4 + 3] = v.w;
    __syncthreads();
    int n = t >> 3, k4 = (t & 7) * 4;
    __half2 lo = __floats2half2_rn(smt[k4 + 0][n], smt[k4 + 1][n]);
    __half2 hi = __floats2half2_rn(smt[k4 + 2][n], smt[k4 + 3][n]);
    hf* d = dst + segOff[seg] + (size_t)(n0 + n) * K + k0 + k4;
    *reinterpret_cast<__half2*>(d)     = lo;
    *reinterpret_cast<__half2*>(d + 2) = hi;
}

// ---------------- LayerNorm core ----------------
__device__ __forceinline__ void ln_row(const float* __restrict__ xr,
                                       const float* __restrict__ scale,
                                       const float* __restrict__ offset,
                                       hf* __restrict__ orow) {
    int t = threadIdx.x;
    float v0 = xr[t], v1 = xr[t + 128], v2 = xr[t + 256];
    float s  = v0 + v1 + v2;
    float s2 = v0 * v0 + v1 * v1 + v2 * v2;
    #pragma unroll
    for (int o = 16; o; o >>= 1) {
        s  += __shfl_down_sync(0xffffffffu, s,  o);
        s2 += __shfl_down_sync(0xffffffffu, s2, o);
    }
    __shared__ float sh[8];
    __shared__ float mu_s, rstd_s;
    int wid = t >> 5, lane = t & 31;
    if (lane == 0) { sh[wid] = s; sh[4 + wid] = s2; }
    __syncthreads();
    if (t == 0) {
        float ts  = sh[0] + sh[1] + sh[2] + sh[3];
        float ts2 = sh[4] + sh[5] + sh[6] + sh[7];
        float mu  = ts * (1.0f / C_DIM);
        float var = ts2 * (1.0f / C_DIM) - mu * mu;
        mu_s = mu; rstd_s = rsqrtf(var + LN_EPS);
    }
    __syncthreads();
    float mu = mu_s, rstd = rstd_s;
    orow[t]       = __float2half_rn(scale[t]       * (v0 - mu) * rstd + offset[t]);
    orow[t + 128] = __float2half_rn(scale[t + 128] * (v1 - mu) * rstd + offset[t + 128]);
    orow[t + 256] = __float2half_rn(scale[t + 256] * (v2 - mu) * rstd + offset[t + 256]);
}

__global__ void ln_kernel(const float* __restrict__ x, const float* __restrict__ scale,
                          const float* __restrict__ offset, hf* __restrict__ out) {
    int row = blockIdx.x;
    ln_row(x + (size_t)row * C_DIM, scale, offset, out + (size_t)row * C_DIM);
}

__global__ void ln_fused_kernel(const float* __restrict__ resampled, const float* __restrict__ original,
                                const float* __restrict__ qn_s, const float* __restrict__ qn_o,
                                const float* __restrict__ dn_s, const float* __restrict__ dn_o,
                                const float* __restrict__ ot_s, const float* __restrict__ ot_o,
                                hf* __restrict__ qin, hf* __restrict__ din, hf* __restrict__ ln4) {
    int row = blockIdx.x;
    if (row < T_TOK) {
        ln_row(resampled + (size_t)row * C_DIM, qn_s, qn_o, qin + (size_t)row * C_DIM);
    } else if (row < T_TOK + N_RES) {
        int r = row - T_TOK;
        ln_row(original + (size_t)r * C_DIM, dn_s, dn_o, din + (size_t)r * C_DIM);
    } else {
        int r = row - T_TOK - N_RES;
        ln_row(original + (size_t)r * C_DIM, ot_s, ot_o, ln4 + (size_t)r * C_DIM);
    }
}

// ---------------- MTx128xBK fp16 GEMM, 4-stage cp.async, m16n8k16 ----------------
// A[M][K] fp16, B = Wt[N][K] fp16. modes: 0=f32(+res), 1=f32 tf32-rounded(+res), 2=fp16
#define ACT_NONE 0
#define ACT_RELU 1
#define ACT_SIGMOID 2

template<int MT>
__global__ __launch_bounds__(256, 2) void gemm_hf(
    const hf* __restrict__ A,
    const hf* __restrict__ B0, void* __restrict__ C0v, float alpha0,
    const float* __restrict__ bias0, int act0, const float* __restrict__ res0, int mode0,
    const hf* __restrict__ B1, void* __restrict__ C1v, float alpha1,
    const float* __restrict__ bias1, int act1, const float* __restrict__ res1, int mode1,
    int M, int N, int K, int halfX) {
    constexpr int A_STAGE = MT * BK;       // halves per A stage
    constexpr int B_STAGE = 128 * BK;
    constexpr int FM = MT / 32;            // m-frags per warp (4 or 2)
    constexpr int AG = MT / 64;            // A granules per thread (2 or 1)
    extern __shared__ hf smg[];
    hf* As = smg;
    hf* Bs = smg + STAGES * A_STAGE;

    int t = threadIdx.x;
    int bxx = blockIdx.x;
    const hf* B = B0; void* Cv = C0v; float alpha = alpha0;
    const float* bias = bias0; int act = act0; const float* residual = res0; int mode = mode0;
    if (bxx >= halfX) {
        bxx -= halfX;
        B = B1; Cv = C1v; alpha = alpha1; bias = bias1; act = act1; residual = res1; mode = mode1;
    }
    int bm = blockIdx.y * MT, bn = bxx * 128;
    int wid = t >> 5, lane = t & 31, grp = lane >> 2, tig = lane & 3;
    int wm = (wid >> 2) * (MT / 2);
    int wn = (wid & 3) * 32;

    // cp.async mapping: granule = 8 halves; swizzle g ^ ((row>>1)&3)
    int a_dst[AG]; size_t a_src[AG];
    #pragma unroll
    for (int i = 0; i < AG; i++) {
        int idx = t + i * 256;
        int m = idx >> 2, g = idx & 3;
        a_dst[i] = (m * 4 + (g ^ ((m >> 1) & 3))) * 8;
        a_src[i] = (size_t)(bm + m) * K + g * 8;
    }
    int b_dst[2]; size_t b_src[2];
    #pragma unroll
    for (int i = 0; i < 2; i++) {
        int idx = t + i * 256;
        int n = idx >> 2, g = idx & 3;
        b_dst[i] = (n * 4 + (g ^ ((n >> 1) & 3))) * 8;
        b_src[i] = (size_t)(bn + n) * K + g * 8;
    }

    float acc[FM][4][4];
    #pragma unroll
    for (int i = 0; i < FM; i++)
        #pragma unroll
        for (int j = 0; j < 4; j++)
            #pragma unroll
            for (int r = 0; r < 4; r++) acc[i][j][r] = 0.0f;

    int kTiles = K / BK;

    #pragma unroll
    for (int pt = 0; pt < STAGES - 1; pt++) {
        hf* ab = As + pt * A_STAGE;
        hf* bb = Bs + pt * B_STAGE;
        #pragma unroll
        for (int i = 0; i < AG; i++) cp16(ab + a_dst[i], A + a_src[i] + pt * BK);
        #pragma unroll
        for (int i = 0; i < 2; i++)  cp16(bb + b_dst[i], B + b_src[i] + pt * BK);
        CP_COMMIT();
    }

    for (int kt = 0; kt < kTiles; kt++) {
        CP_WAIT(STAGES - 2);
        __syncthreads();
        int nt = kt + STAGES - 1;
        if (nt < kTiles) {
            int buf = nt % STAGES;
            hf* ab = As + buf * A_STAGE;
            hf* bb = Bs + buf * B_STAGE;
            #pragma unroll
            for (int i = 0; i < AG; i++) cp16(ab + a_dst[i], A + a_src[i] + nt * BK);
            #pragma unroll
            for (int i = 0; i < 2; i++)  cp16(bb + b_dst[i], B + b_src[i] + nt * BK);
        }
        CP_COMMIT();
        const hf* as = As + (kt % STAGES) * A_STAGE;
        const hf* bs = Bs + (kt % STAGES) * B_STAGE;
        #pragma unroll
        for (int s = 0; s < 2; s++) {           // 2 x k16 steps
            unsigned af[FM][4];
            #pragma unroll
            for (int fm = 0; fm < FM; fm++) {
                int m = wm + fm * 16 + grp;
                int sw = (m >> 1) & 3;
                int g0 = (2 * s) ^ sw, g1 = (2 * s + 1) ^ sw;
                af[fm][0] = *reinterpret_cast<const unsigned*>(as + m * BK + g0 * 8 + tig * 2);
                af[fm][1] = *reinterpret_cast<const unsigned*>(as + (m + 8) * BK + g0 * 8 + tig * 2);
                af[fm][2] = *reinterpret_cast<const unsigned*>(as + m * BK + g1 * 8 + tig * 2);
                af[fm][3] = *reinterpret_cast<const unsigned*>(as + (m + 8) * BK + g1 * 8 + tig * 2);
            }
            unsigned bfr[4][2];
            #pragma unroll
            for (int fn = 0; fn < 4; fn++) {
                int n = wn + fn * 8 + grp;
                int sw = (n >> 1) & 3;
                int g0 = (2 * s) ^ sw, g1 = (2 * s + 1) ^ sw;
                bfr[fn][0] = *reinterpret_cast<const unsigned*>(bs + n * BK + g0 * 8 + tig * 2);
                bfr[fn][1] = *reinterpret_cast<const unsigned*>(bs + n * BK + g1 * 8 + tig * 2);
            }
            #pragma unroll
            for (int fm = 0; fm < FM; fm++)
                #pragma unroll
                for (int fn = 0; fn < 4; fn++)
                    MMA_F16(acc[fm][fn], af[fm], bfr[fn]);
        }
        __syncthreads();
    }

    #pragma unroll
    for (int fm = 0; fm < FM; fm++) {
        #pragma unroll
        for (int fn = 0; fn < 4; fn++) {
            int m0 = bm + wm + fm * 16 + grp;
            int n  = bn + wn + fn * 8 + tig * 2;
            #pragma unroll
            for (int half = 0; half < 2; half++) {
                int m = m0 + half * 8;
                float x0 = acc[fm][fn][half * 2 + 0] * alpha;
                float x1 = acc[fm][fn][half * 2 + 1] * alpha;
                if (bias) { x0 += bias[n]; x1 += bias[n + 1]; }
                if (act == ACT_RELU) {
                    x0 = fmaxf(x0, 0.0f); x1 = fmaxf(x1, 0.0f);
                } else if (act == ACT_SIGMOID) {
                    x0 = 1.0f / (1.0f + __expf(-x0));
                    x1 = 1.0f / (1.0f + __expf(-x1));
                }
                if (mode == 2) {
                    hf* Cb = (hf*)Cv;
                    *reinterpret_cast<__half2*>(&Cb[(size_t)m * N + n]) =
                        __floats2half2_rn(x0, x1);
                } else {
                    float* Cf = (float*)Cv;
                    if (residual) {
                        float2 r = *reinterpret_cast<const float2*>(&residual[(size_t)m * N + n]);
                        x0 += r.x; x1 += r.y;
                    }
                    if (mode == 1) { x0 = to_tf32(x0); x1 = to_tf32(x1); }
                    *reinterpret_cast<float2*>(&Cf[(size_t)m * N + n]) = make_float2(x0, x1);
                }
            }
        }
    }
}

// ---------------- flash attention (tf32) ----------------
#define QS_PITCH 52
#define VS_PITCH 56
#define MS_PITCH 68
#define FL_QS 0
#define FL_KS (64*52)
#define FL_VS (FL_KS + 2*64*52)
#define FL_MS (FL_VS + 2*64*56)
#define FL_TOTAL (FL_MS + 2*64*68)

__global__ __launch_bounds__(128) void flash_kernel(
    const float* __restrict__ q, const float* __restrict__ k,
    const float* __restrict__ v, const float* __restrict__ mask,
    float* __restrict__ po, float* __restrict__ pm, float* __restrict__ pl) {
    extern __shared__ float sm[];
    float* Qs = sm + FL_QS;
    int t = threadIdx.x;
    int wid = t >> 5, lane = t & 31, grp = lane >> 2, tig = lane & 3;
    int t0 = blockIdx.x * 64;
    int h  = blockIdx.y;
    int rsp = blockIdx.z;
    int rbase = rsp * (N_RES / RSPLIT);
    int wr = wid * 16;

    for (int i = t; i < 64 * 12; i += 128) {
        int r = i / 12, f = i % 12;
        float4 q4 = *reinterpret_cast<const float4*>(&q[(size_t)(t0 + r) * C_DIM + h * KD + f * 4]);
        *reinterpret_cast<float4*>(&Qs[r * QS_PITCH + f * 4]) = q4;
    }

    const int NCH = (N_RES / RSPLIT) / RCHUNK;

    auto issue = [&](int ch, int b) {
        int r0 = rbase + ch * RCHUNK;
        float* ks = sm + FL_KS + b * 64 * QS_PITCH;
        float* vs = sm + FL_VS + b * 64 * VS_PITCH;
        float* ms = sm + FL_MS + b * 64 * MS_PITCH;
        for (int i = t; i < 64 * 12; i += 128) {
            int r = i / 12, f = i % 12;
            size_t src = (size_t)(r0 + r) * C_DIM + h * KD + f * 4;
            cp16(&ks[r * QS_PITCH + f * 4], &k[src]);
            cp16(&vs[r * VS_PITCH + f * 4], &v[src]);
        }
        for (int i = t; i < 64 * 16; i += 128) {
            int rr = i / 16, f = i % 16;
            cp16(&ms[rr * MS_PITCH + f * 4],
                 &mask[((size_t)h * T_TOK + t0 + rr) * N_RES + r0 + f * 4]);
        }
    };

    issue(0, 0); CP_COMMIT();
    issue(1, 1); CP_COMMIT();

    float m_lo = -1e30f, m_hi = -1e30f, l_lo = 0.0f, l_hi = 0.0f;
    float acc_o[6][4];
    #pragma unroll
    for (int i = 0; i < 6; i++)
        #pragma unroll
        for (int e = 0; e < 4; e++) acc_o[i][e] = 0.0f;

    for (int ch = 0; ch < NCH; ch++) {
        int b = ch & 1;
        CP_WAIT(1);
        __syncthreads();
        float* ks = sm + FL_KS + b * 64 * QS_PITCH;
        float* vs = sm + FL_VS + b * 64 * VS_PITCH;
        float* ms = sm + FL_MS + b * 64 * MS_PITCH;

        float acc_s[8][4];
        #pragma unroll
        for (int fn = 0; fn < 8; fn++)
            #pragma unroll
            for (int e = 0; e < 4; e++) acc_s[fn][e] = 0.0f;
        #pragma unroll
        for (int s = 0; s < 6; s++) {
            int k0 = s * 8;
            unsigned a[4];
            a[0] = __float_as_uint(Qs[(wr + grp) * QS_PITCH + k0 + tig]);
            a[1] = __float_as_uint(Qs[(wr + grp + 8) * QS_PITCH + k0 + tig]);
            a[2] = __float_as_uint(Qs[(wr + grp) * QS_PITCH + k0 + 4 + tig]);
            a[3] = __float_as_uint(Qs[(wr + grp + 8) * QS_PITCH + k0 + 4 + tig]);
            #pragma unroll
            for (int fn = 0; fn < 8; fn++) {
                unsigned bb[2];
                bb[0] = __float_as_uint(ks[(fn * 8 + grp) * QS_PITCH + k0 + tig]);
                bb[1] = __float_as_uint(ks[(fn * 8 + grp) * QS_PITCH + k0 + 4 + tig]);
                MMA_TF32(acc_s[fn], a, bb);
            }
        }
        float mx_lo = -1e30f, mx_hi = -1e30f;
        #pragma unroll
        for (int fn = 0; fn < 8; fn++) {
            int col = fn * 8 + 2 * tig;
            float2 blo = *reinterpret_cast<float2*>(&ms[(wr + grp) * MS_PITCH + col]);
            float2 bhi = *reinterpret_cast<float2*>(&ms[(wr + grp + 8) * MS_PITCH + col]);
            acc_s[fn][0] += BIGF * (blo.x - 1.0f);
            acc_s[fn][1] += BIGF * (blo.y - 1.0f);
            acc_s[fn][2] += BIGF * (bhi.x - 1.0f);
            acc_s[fn][3] += BIGF * (bhi.y - 1.0f);
            mx_lo = fmaxf(mx_lo, fmaxf(acc_s[fn][0], acc_s[fn][1]));
            mx_hi = fmaxf(mx_hi, fmaxf(acc_s[fn][2], acc_s[fn][3]));
        }
        mx_lo = fmaxf(mx_lo, __shfl_xor_sync(0xffffffffu, mx_lo, 1));
        mx_lo = fmaxf(mx_lo, __shfl_xor_sync(0xffffffffu, mx_lo, 2));
        mx_hi = fmaxf(mx_hi, __shfl_xor_sync(0xffffffffu, mx_hi, 1));
        mx_hi = fmaxf(mx_hi, __shfl_xor_sync(0xffffffffu, mx_hi, 2));
        float mn_lo = fmaxf(m_lo, mx_lo), mn_hi = fmaxf(m_hi, mx_hi);
        float sc_lo = __expf(m_lo - mn_lo), sc_hi = __expf(m_hi - mn_hi);
        m_lo = mn_lo; m_hi = mn_hi;
        float rs_lo = 0.0f, rs_hi = 0.0f;
        #pragma unroll
        for (int fn = 0; fn < 8; fn++) {
            int col = fn * 8 + 2 * tig;
            float p0 = __expf(acc_s[fn][0] - mn_lo);
            float p1 = __expf(acc_s[fn][1] - mn_lo);
            float p2 = __expf(acc_s[fn][2] - mn_hi);
            float p3 = __expf(acc_s[fn][3] - mn_hi);
            rs_lo += p0 + p1; rs_hi += p2 + p3;
            *reinterpret_cast<float2*>(&ms[(wr + grp) * MS_PITCH + col]) =
                make_float2(to_tf32(p0), to_tf32(p1));
            *reinterpret_cast<float2*>(&ms[(wr + grp + 8) * MS_PITCH + col]) =
                make_float2(to_tf32(p2), to_tf32(p3));
        }
        rs_lo += __shfl_xor_sync(0xffffffffu, rs_lo, 1);
        rs_lo += __shfl_xor_sync(0xffffffffu, rs_lo, 2);
        rs_hi += __shfl_xor_sync(0xffffffffu, rs_hi, 1);
        rs_hi += __shfl_xor_sync(0xffffffffu, rs_hi, 2);
        l_lo = l_lo * sc_lo + rs_lo;
        l_hi = l_hi * sc_hi + rs_hi;
        #pragma unroll
        for (int fn = 0; fn < 6; fn++) {
            acc_o[fn][0] *= sc_lo; acc_o[fn][1] *= sc_lo;
            acc_o[fn][2] *= sc_hi; acc_o[fn][3] *= sc_hi;
        }
        __syncwarp();
        #pragma unroll
        for (int s = 0; s < 8; s++) {
            int k0 = s * 8;
            unsigned a[4];
            a[0] = __float_as_uint(ms[(wr + grp) * MS_PITCH + k0 + tig]);
            a[1] = __float_as_uint(ms[(wr + grp + 8) * MS_PITCH + k0 + tig]);
            a[2] = __float_as_uint(ms[(wr + grp) * MS_PITCH + k0 + 4 + tig]);
            a[3] = __float_as_uint(ms[(wr + grp + 8) * MS_PITCH + k0 + 4 + tig]);
            #pragma unroll
            for (int fn = 0; fn < 6; fn++) {
                unsigned bb[2];
                bb[0] = __float_as_uint(vs[(k0 + tig) * VS_PITCH + fn * 8 + grp]);
                bb[1] = __float_as_uint(vs[(k0 + 4 + tig) * VS_PITCH + fn * 8 + grp]);
                MMA_TF32(acc_o[fn], a, bb);
            }
        }
        __syncthreads();
        if (ch + 2 < NCH) issue(ch + 2, b);
        CP_COMMIT();
    }

    int row_lo = (rsp * H_HEADS + h) * T_TOK + t0 + wr + grp;
    int row_hi = row_lo + 8;
    #pragma unroll
    for (int fn = 0; fn < 6; fn++) {
        int c = fn * 8 + 2 * tig;
        *reinterpret_cast<float2*>(&po[(size_t)row_lo * KD + c]) =
            make_float2(acc_o[fn][0], acc_o[fn][1]);
        *reinterpret_cast<float2*>(&po[(size_t)row_hi * KD + c]) =
            make_float2(acc_o[fn][2], acc_o[fn][3]);
    }
    if (tig == 0) {
        pm[row_lo] = m_lo; pm[row_hi] = m_hi;
        pl[row_lo] = l_lo; pl[row_hi] = l_hi;
    }
}

// ---------------- combine r-splits, apply gate, write wag fp16 ----------------
__global__ void combine_kernel(const float* __restrict__ po, const float* __restrict__ pm,
                               const float* __restrict__ pl, const float* __restrict__ gate,
                               hf* __restrict__ wag) {
    int idx = blockIdx.x * 256 + threadIdx.x;
    const int TOT = H_HEADS * T_TOK * KD;
    const int HT  = H_HEADS * T_TOK;
    if (idx >= TOT) return;
    int c  = idx % KD;
    int ht = idx / KD;
    int tt = ht % T_TOK, h = ht / T_TOK;
    float mm = -1e30f;
    #pragma unroll
    for (int r = 0; r < RSPLIT; r++) mm = fmaxf(mm, pm[r * HT + ht]);
    float l = 0.0f, o = 0.0f;
    #pragma unroll
    for (int r = 0; r < RSPLIT; r++) {
        float s = __expf(pm[r * HT + ht] - mm);
        l += pl[r * HT + ht] * s;
        o += po[(size_t)r * TOT + idx] * s;
    }
    o /= l;
    float g = gate[(size_t)tt * C_DIM + h * KD + c];
    wag[(size_t)tt * C_DIM + h * KD + c] = __float2half_rn(o * g);
}

// ---------------- host launch ----------------
static void* symv(const void* s) {
    void* p = nullptr;
    cudaGetSymbolAddress(&p, s);
    return p;
}

extern "C" void kernel_launch(void* const* d_in, const int* in_sizes, int n_in,
                              void* d_out, int out_size) {
    const float* original   = (const float*)d_in[0];
    const float* resampled  = (const float*)d_in[1];
    const float* attn_mask  = (const float*)d_in[2];
    const float* qn_scale   = (const float*)d_in[5];
    const float* qn_offset  = (const float*)d_in[6];
    const float* dn_scale   = (const float*)d_in[7];
    const float* dn_offset  = (const float*)d_in[8];
    const float* query_w    = (const float*)d_in[9];
    const float* key_w      = (const float*)d_in[10];
    const float* value_w    = (const float*)d_in[11];
    const float* gating_w   = (const float*)d_in[12];
    const float* gating_b   = (const float*)d_in[13];
    const float* output_w   = (const float*)d_in[14];
    const float* output_b   = (const float*)d_in[15];
    const float* rt_ln_scale  = (const float*)d_in[16];
    const float* rt_ln_offset = (const float*)d_in[17];
    const float* rt_w1 = (const float*)d_in[18];
    const float* rt_b1 = (const float*)d_in[19];
    const float* rt_w2 = (const float*)d_in[20];
    const float* rt_b2 = (const float*)d_in[21];
    const float* ot_ln_scale  = (const float*)d_in[22];
    const float* ot_ln_offset = (const float*)d_in[23];
    const float* ot_w1 = (const float*)d_in[24];
    const float* ot_b1 = (const float*)d_in[25];
    const float* ot_w2 = (const float*)d_in[26];
    const float* ot_b2 = (const float*)d_in[27];

    float* out_res  = (float*)d_out;
    float* out_orig = out_res + (size_t)T_TOK * C_DIM;

    hf*    p_qin  = (hf*)symv(g_qin);
    hf*    p_din  = (hf*)symv(g_din);
    hf*    p_ln4  = (hf*)symv(g_ln4);
    float* p_q    = (float*)symv(g_q);
    float* p_gate = (float*)symv(g_gate);
    float* p_k    = (float*)symv(g_k);
    float* p_v    = (float*)symv(g_v);
    hf*    p_wag  = (hf*)symv(g_wag);
    hf*    p_ln3  = (hf*)symv(g_ln3);
    hf*    p_h1   = (hf*)symv(g_h1);
    hf*    p_h2   = (hf*)symv(g_h2);
    hf*    p_wts  = (hf*)symv(g_wts);
    float* p_po   = (float*)symv(g_po);
    float* p_pm   = (float*)symv(g_pm);
    float* p_pl   = (float*)symv(g_pl);

    const int smem128 = STAGES * (128 * BK + 128 * BK) * 2;   // 65536 B
    const int smem64  = STAGES * (64 * BK + 128 * BK) * 2;    // 49152 B
    const int flash_smem = FL_TOTAL * 4;
    cudaFuncSetAttribute(gemm_hf<128>, cudaFuncAttributeMaxDynamicSharedMemorySize, smem128);
    cudaFuncSetAttribute(gemm_hf<64>,  cudaFuncAttributeMaxDynamicSharedMemorySize, smem64);
    cudaFuncSetAttribute(flash_kernel, cudaFuncAttributeMaxDynamicSharedMemorySize, flash_smem);

    const float inv_sqrt_kd = 0.14433756729740643f;
    const int BIG_HALF = 1 << 30;

    // ONE side stream (stream objects cost ~1MB device memory each; the guard
    // allows the single-stream pattern proven in earlier rounds).
    cudaStream_t s2 = 0;
    cudaEvent_t ev_root = 0, ev_ln = 0, ev_w = 0, ev_ot = 0;
    cudaStreamCreateWithFlags(&s2, cudaStreamNonBlocking);
    cudaEventCreateWithFlags(&ev_root, cudaEventDisableTiming);
    cudaEventCreateWithFlags(&ev_ln, cudaEventDisableTiming);
    cudaEventCreateWithFlags(&ev_w,  cudaEventDisableTiming);
    cudaEventCreateWithFlags(&ev_ot, cudaEventDisableTiming);
    bool fork_ok = s2 && ev_root && ev_ln && ev_w && ev_ot;

    SrcPtrs sp;
    sp.p[0] = query_w;  sp.p[1] = key_w;  sp.p[2] = value_w;
    sp.p[3] = gating_w; sp.p[4] = output_w;
    sp.p[5] = rt_w1;    sp.p[6] = rt_w2;  sp.p[7] = ot_w1; sp.p[8] = ot_w2;

    if (fork_ok) {
        // fork s2 from capturing stream FIRST
        cudaEventRecord(ev_root, 0);
        cudaStreamWaitEvent(s2, ev_root, 0);

        // wt on s2 (concurrent with LN on stream 0)
        wt_kernel<<<3024, 256, 0, s2>>>(sp, p_wts);
        cudaEventRecord(ev_w, s2);

        ln_fused_kernel<<<T_TOK + 2 * N_RES, 128>>>(resampled, original,
            qn_scale, qn_offset, dn_scale, dn_offset, ot_ln_scale, ot_ln_offset,
            p_qin, p_din, p_ln4);
        cudaEventRecord(ev_ln, 0);

        // s2: wait LN, then ot branch (wt already ordered on s2)
        cudaStreamWaitEvent(s2, ev_ln, 0);
        gemm_hf<128><<<dim3(12, 32), 256, smem128, s2>>>(p_ln4,
            p_wts + OFF_OT1, p_h2, 1.0f, ot_b1, ACT_RELU, nullptr, 2,
            nullptr, nullptr, 0.0f, nullptr, 0, nullptr, 0,
            N_RES, F_DIM, C_DIM, BIG_HALF);
        gemm_hf<64><<<dim3(3, 64), 256, smem64, s2>>>(p_h2,
            p_wts + OFF_OT2, out_orig, 1.0f, ot_b2, ACT_NONE, original, 0,
            nullptr, nullptr, 0.0f, nullptr, 0, nullptr, 0,
            N_RES, C_DIM, F_DIM, BIG_HALF);
        cudaEventRecord(ev_ot, s2);

        // main chain: wait for weights
        cudaStreamWaitEvent(0, ev_w, 0);
    } else {
        wt_kernel<<<3024, 256>>>(sp, p_wts);
        ln_fused_kernel<<<T_TOK + 2 * N_RES, 128>>>(resampled, original,
            qn_scale, qn_offset, dn_scale, dn_offset, ot_ln_scale, ot_ln_offset,
            p_qin, p_din, p_ln4);
        gemm_hf<128><<<dim3(12, 32), 256, smem128>>>(p_ln4,
            p_wts + OFF_OT1, p_h2, 1.0f, ot_b1, ACT_RELU, nullptr, 2,
            nullptr, nullptr, 0.0f, nullptr, 0, nullptr, 0,
            N_RES, F_DIM, C_DIM, BIG_HALF);
        gemm_hf<64><<<dim3(3, 64), 256, smem64>>>(p_h2,
            p_wts + OFF_OT2, out_orig, 1.0f, ot_b2, ACT_NONE, original, 0,
            nullptr, nullptr, 0.0f, nullptr, 0, nullptr, 0,
            N_RES, C_DIM, F_DIM, BIG_HALF);
    }

    // main chain
    gemm_hf<64><<<dim3(6, 8), 256, smem64>>>(p_qin,
        p_wts + OFF_QW, p_q, inv_sqrt_kd, nullptr, ACT_NONE, nullptr, 1,
        p_wts + OFF_GW, p_gate, 1.0f, gating_b, ACT_SIGMOID, nullptr, 0,
        T_TOK, C_DIM, C_DIM, 3);
    gemm_hf<128><<<dim3(6, 32), 256, smem128>>>(p_din,
        p_wts + OFF_KW, p_k, 1.0f, nullptr, ACT_NONE, nullptr, 1,
        p_wts + OFF_VW, p_v, 1.0f, nullptr, ACT_NONE, nullptr, 1,
        N_RES, C_DIM, C_DIM, 3);

    flash_kernel<<<dim3(T_TOK / 64, H_HEADS, RSPLIT), 128, flash_smem>>>(
        p_q, p_k, p_v, attn_mask, p_po, p_pm, p_pl);
    combine_kernel<<<(H_HEADS * T_TOK * KD + 255) / 256, 256>>>(p_po, p_pm, p_pl, p_gate, p_wag);

    gemm_hf<64><<<dim3(3, 8), 256, smem64>>>(p_wag,
        p_wts + OFF_OW, out_res, 1.0f, output_b, ACT_NONE, resampled, 0,
        nullptr, nullptr, 0.0f, nullptr, 0, nullptr, 0,
        T_TOK, C_DIM, C_DIM, BIG_HALF);

    ln_kernel<<<T_TOK, 128>>>(out_res, rt_ln_scale, rt_ln_offset, p_ln3);
    gemm_hf<64><<<dim3(12, 8), 256, smem64>>>(p_ln3,
        p_wts + OFF_RT1, p_h1, 1.0f, rt_b1, ACT_RELU, nullptr, 2,
        nullptr, nullptr, 0.0f, nullptr, 0, nullptr, 0,
        T_TOK, F_DIM, C_DIM, BIG_HALF);
    gemm_hf<64><<<dim3(3, 8), 256, smem64>>>(p_h1,
        p_wts + OFF_RT2, out_res, 1.0f, rt_b2, ACT_NONE, out_res, 0,
        nullptr, nullptr, 0.0f, nullptr, 0, nullptr, 0,
        T_TOK, C_DIM, F_DIM, BIG_HALF);

    if (fork_ok) cudaStreamWaitEvent(0, ev_ot, 0);
}

// round 15
// speedup vs baseline: 1.6295x; 1.0827x over previous
#include <cuda_runtime.h>
#include <cuda_fp16.h>
#include <math.h>

#define T_TOK 512
#define N_RES 4096
#define C_DIM 384
#define H_HEADS 8
#define KD 48
#define F_DIM 1536
#define LN_EPS 1e-5f
#define BIGF 1e9f
#define RSPLIT 4
#define RCHUNK 64
#define STAGES 4
#define BK 32

typedef __half hf;

// ---------------- scratch (device globals) ----------------
__device__ hf    g_qin [T_TOK * C_DIM];
__device__ hf    g_din [N_RES * C_DIM];
__device__ hf    g_ln4 [N_RES * C_DIM];
__device__ hf    g_qh  [T_TOK * C_DIM];      // fp16 q (pre-scaled)
__device__ hf    g_kh  [N_RES * C_DIM];      // fp16 k
__device__ float g_gate[T_TOK * C_DIM];
__device__ float g_v   [N_RES * C_DIM];
__device__ hf    g_wag [T_TOK * C_DIM];
__device__ hf    g_ln3 [T_TOK * C_DIM];
__device__ hf    g_h1  [T_TOK * F_DIM];
__device__ hf    g_h2  [N_RES * F_DIM];
// fp16 TRANSPOSED weights Wt[N][K] (element offsets)
#define OFF_QW  0
#define OFF_KW  147456
#define OFF_VW  294912
#define OFF_GW  442368
#define OFF_OW  589824
#define OFF_RT1 737280
#define OFF_RT2 1327104
#define OFF_OT1 1916928
#define OFF_OT2 2506752
#define WTS_TOTAL 3096576
__device__ hf g_wts[WTS_TOTAL];
// flash partials
__device__ float g_po[RSPLIT * H_HEADS * T_TOK * KD];
__device__ float g_pm[RSPLIT * H_HEADS * T_TOK];
__device__ float g_pl[RSPLIT * H_HEADS * T_TOK];

__device__ __forceinline__ float to_tf32(float x) {
    asm("cvt.rna.tf32.f32 %0, %1;" : "=f"(x) : "f"(x));
    return x;
}

#define MMA_TF32(c, a, b) \
    asm volatile("mma.sync.aligned.m16n8k8.row.col.f32.tf32.tf32.f32 " \
        "{%0,%1,%2,%3}, {%4,%5,%6,%7}, {%8,%9}, {%0,%1,%2,%3};" \
        : "+f"((c)[0]), "+f"((c)[1]), "+f"((c)[2]), "+f"((c)[3]) \
        : "r"((a)[0]), "r"((a)[1]), "r"((a)[2]), "r"((a)[3]), \
          "r"((b)[0]), "r"((b)[1]))

#define MMA_F16(c, a, b) \
    asm volatile("mma.sync.aligned.m16n8k16.row.col.f32.f16.f16.f32 " \
        "{%0,%1,%2,%3}, {%4,%5,%6,%7}, {%8,%9}, {%0,%1,%2,%3};" \
        : "+f"((c)[0]), "+f"((c)[1]), "+f"((c)[2]), "+f"((c)[3]) \
        : "r"((a)[0]), "r"((a)[1]), "r"((a)[2]), "r"((a)[3]), \
          "r"((b)[0]), "r"((b)[1]))

__device__ __forceinline__ void cp16(void* dst, const void* src) {
    unsigned d = (unsigned)__cvta_generic_to_shared(dst);
    asm volatile("cp.async.ca.shared.global [%0], [%1], 16;" :: "r"(d), "l"(src));
}
#define CP_COMMIT() asm volatile("cp.async.commit_group;")
#define CP_WAIT(n)  asm volatile("cp.async.wait_group %0;" :: "n"(n))

// ---------------- weight transpose + fp16 convert: W[K][N] fp32 -> Wt[N][K] fp16 ----------------
struct SrcPtrs { const float* p[9]; };

__global__ __launch_bounds__(256) void wt_kernel(SrcPtrs s, hf* __restrict__ dst) {
    const int segK[9]   = {384, 384, 384, 384, 384, 384, 1536, 384, 1536};
    const int segN[9]   = {384, 384, 384, 384, 384, 1536, 384, 1536, 384};
    const int segOff[9] = {OFF_QW, OFF_KW, OFF_VW, OFF_GW, OFF_OW, OFF_RT1, OFF_RT2, OFF_OT1, OFF_OT2};
    const int cum[10]   = {0, 144, 288, 432, 576, 720, 1296, 1872, 2448, 3024};
    int b = blockIdx.x;
    int seg = 0;
    #pragma unroll
    for (int i = 1; i < 9; i++) if (b >= cum[i]) seg = i;
    int tile = b - cum[seg];
    int K = segK[seg], N = segN[seg];
    int ntn = N >> 5;
    int k0 = (tile / ntn) * 32, n0 = (tile % ntn) * 32;
    const float* src = s.p[seg];

    __shared__ float smt[32][33];
    int t = threadIdx.x;
    int r = t >> 3, c4 = (t & 7) * 4;
    float4 v = *reinterpret_cast<const float4*>(&src[(size_t)(k0 + r) * N + n0 + c4]);
    smt[r][c4 + 0] = v.x; smt[r][c4 + 1] = v.y;
    smt[r][c4 + 2] = v.z; smt[r][c4 + 3] = v.w;
    __syncthreads();
    int n = t >> 3, k4 = (t & 7) * 4;
    __half2 lo = __floats2half2_rn(smt[k4 + 0][n], smt[k4 + 1][n]);
    __half2 hi = __floats2half2_rn(smt[k4 + 2][n], smt[k4 + 3][n]);
    hf* d = dst + segOff[seg] + (size_t)(n0 + n) * K + k0 + k4;
    *reinterpret_cast<__half2*>(d)     = lo;
    *reinterpret_cast<__half2*>(d + 2) = hi;
}

// ---------------- LayerNorm core ----------------
__device__ __forceinline__ void ln_row(const float* __restrict__ xr,
                                       const float* __restrict__ scale,
                                       const float* __restrict__ offset,
                                       hf* __restrict__ orow) {
    int t = threadIdx.x;
    float v0 = xr[t], v1 = xr[t + 128], v2 = xr[t + 256];
    float s  = v0 + v1 + v2;
    float s2 = v0 * v0 + v1 * v1 + v2 * v2;
    #pragma unroll
    for (int o = 16; o; o >>= 1) {
        s  += __shfl_down_sync(0xffffffffu, s,  o);
        s2 += __shfl_down_sync(0xffffffffu, s2, o);
    }
    __shared__ float sh[8];
    __shared__ float mu_s, rstd_s;
    int wid = t >> 5, lane = t & 31;
    if (lane == 0) { sh[wid] = s; sh[4 + wid] = s2; }
    __syncthreads();
    if (t == 0) {
        float ts  = sh[0] + sh[1] + sh[2] + sh[3];
        float ts2 = sh[4] + sh[5] + sh[6] + sh[7];
        float mu  = ts * (1.0f / C_DIM);
        float var = ts2 * (1.0f / C_DIM) - mu * mu;
        mu_s = mu; rstd_s = rsqrtf(var + LN_EPS);
    }
    __syncthreads();
    float mu = mu_s, rstd = rstd_s;
    orow[t]       = __float2half_rn(scale[t]       * (v0 - mu) * rstd + offset[t]);
    orow[t + 128] = __float2half_rn(scale[t + 128] * (v1 - mu) * rstd + offset[t + 128]);
    orow[t + 256] = __float2half_rn(scale[t + 256] * (v2 - mu) * rstd + offset[t + 256]);
}

__global__ void ln_kernel(const float* __restrict__ x, const float* __restrict__ scale,
                          const float* __restrict__ offset, hf* __restrict__ out) {
    int row = blockIdx.x;
    ln_row(x + (size_t)row * C_DIM, scale, offset, out + (size_t)row * C_DIM);
}

__global__ void ln_fused_kernel(const float* __restrict__ resampled, const float* __restrict__ original,
                                const float* __restrict__ qn_s, const float* __restrict__ qn_o,
                                const float* __restrict__ dn_s, const float* __restrict__ dn_o,
                                const float* __restrict__ ot_s, const float* __restrict__ ot_o,
                                hf* __restrict__ qin, hf* __restrict__ din, hf* __restrict__ ln4) {
    int row = blockIdx.x;
    if (row < T_TOK) {
        ln_row(resampled + (size_t)row * C_DIM, qn_s, qn_o, qin + (size_t)row * C_DIM);
    } else if (row < T_TOK + N_RES) {
        int r = row - T_TOK;
        ln_row(original + (size_t)r * C_DIM, dn_s, dn_o, din + (size_t)r * C_DIM);
    } else {
        int r = row - T_TOK - N_RES;
        ln_row(original + (size_t)r * C_DIM, ot_s, ot_o, ln4 + (size_t)r * C_DIM);
    }
}

// ---------------- MTx128xBK fp16 GEMM, 4-stage cp.async, m16n8k16, single barrier/k-tile ----------------
// A[M][K] fp16, B = Wt[N][K] fp16. modes: 0=f32(+res), 1=f32 tf32-rounded(+res), 2=fp16
#define ACT_NONE 0
#define ACT_RELU 1
#define ACT_SIGMOID 2

template<int MT>
__global__ __launch_bounds__(256, 2) void gemm_hf(
    const hf* __restrict__ A,
    const hf* __restrict__ B0, void* __restrict__ C0v, float alpha0,
    const float* __restrict__ bias0, int act0, const float* __restrict__ res0, int mode0,
    const hf* __restrict__ B1, void* __restrict__ C1v, float alpha1,
    const float* __restrict__ bias1, int act1, const float* __restrict__ res1, int mode1,
    int M, int N, int K, int halfX) {
    constexpr int A_STAGE = MT * BK;
    constexpr int B_STAGE = 128 * BK;
    constexpr int FM = MT / 32;
    constexpr int AG = MT / 64;
    extern __shared__ hf smg[];
    hf* As = smg;
    hf* Bs = smg + STAGES * A_STAGE;

    int t = threadIdx.x;
    int bxx = blockIdx.x;
    const hf* B = B0; void* Cv = C0v; float alpha = alpha0;
    const float* bias = bias0; int act = act0; const float* residual = res0; int mode = mode0;
    if (bxx >= halfX) {
        bxx -= halfX;
        B = B1; Cv = C1v; alpha = alpha1; bias = bias1; act = act1; residual = res1; mode = mode1;
    }
    int bm = blockIdx.y * MT, bn = bxx * 128;
    int wid = t >> 5, lane = t & 31, grp = lane >> 2, tig = lane & 3;
    int wm = (wid >> 2) * (MT / 2);
    int wn = (wid & 3) * 32;

    int a_dst[AG]; size_t a_src[AG];
    #pragma unroll
    for (int i = 0; i < AG; i++) {
        int idx = t + i * 256;
        int m = idx >> 2, g = idx & 3;
        a_dst[i] = (m * 4 + (g ^ ((m >> 1) & 3))) * 8;
        a_src[i] = (size_t)(bm + m) * K + g * 8;
    }
    int b_dst[2]; size_t b_src[2];
    #pragma unroll
    for (int i = 0; i < 2; i++) {
        int idx = t + i * 256;
        int n = idx >> 2, g = idx & 3;
        b_dst[i] = (n * 4 + (g ^ ((n >> 1) & 3))) * 8;
        b_src[i] = (size_t)(bn + n) * K + g * 8;
    }

    float acc[FM][4][4];
    #pragma unroll
    for (int i = 0; i < FM; i++)
        #pragma unroll
        for (int j = 0; j < 4; j++)
            #pragma unroll
            for (int r = 0; r < 4; r++) acc[i][j][r] = 0.0f;

    int kTiles = K / BK;

    #pragma unroll
    for (int pt = 0; pt < STAGES - 1; pt++) {
        hf* ab = As + pt * A_STAGE;
        hf* bb = Bs + pt * B_STAGE;
        #pragma unroll
        for (int i = 0; i < AG; i++) cp16(ab + a_dst[i], A + a_src[i] + pt * BK);
        #pragma unroll
        for (int i = 0; i < 2; i++)  cp16(bb + b_dst[i], B + b_src[i] + pt * BK);
        CP_COMMIT();
    }

    for (int kt = 0; kt < kTiles; kt++) {
        CP_WAIT(STAGES - 2);
        __syncthreads();     // single barrier: orders prior compute before refill below
        int nt = kt + STAGES - 1;
        if (nt < kTiles) {
            int buf = nt % STAGES;
            hf* ab = As + buf * A_STAGE;
            hf* bb = Bs + buf * B_STAGE;
            #pragma unroll
            for (int i = 0; i < AG; i++) cp16(ab + a_dst[i], A + a_src[i] + nt * BK);
            #pragma unroll
            for (int i = 0; i < 2; i++)  cp16(bb + b_dst[i], B + b_src[i] + nt * BK);
        }
        CP_COMMIT();
        const hf* as = As + (kt % STAGES) * A_STAGE;
        const hf* bs = Bs + (kt % STAGES) * B_STAGE;
        #pragma unroll
        for (int s = 0; s < 2; s++) {
            unsigned af[FM][4];
            #pragma unroll
            for (int fm = 0; fm < FM; fm++) {
                int m = wm + fm * 16 + grp;
                int sw = (m >> 1) & 3;
                int g0 = (2 * s) ^ sw, g1 = (2 * s + 1) ^ sw;
                af[fm][0] = *reinterpret_cast<const unsigned*>(as + m * BK + g0 * 8 + tig * 2);
                af[fm][1] = *reinterpret_cast<const unsigned*>(as + (m + 8) * BK + g0 * 8 + tig * 2);
                af[fm][2] = *reinterpret_cast<const unsigned*>(as + m * BK + g1 * 8 + tig * 2);
                af[fm][3] = *reinterpret_cast<const unsigned*>(as + (m + 8) * BK + g1 * 8 + tig * 2);
            }
            unsigned bfr[4][2];
            #pragma unroll
            for (int fn = 0; fn < 4; fn++) {
                int n = wn + fn * 8 + grp;
                int sw = (n >> 1) & 3;
                int g0 = (2 * s) ^ sw, g1 = (2 * s + 1) ^ sw;
                bfr[fn][0] = *reinterpret_cast<const unsigned*>(bs + n * BK + g0 * 8 + tig * 2);
                bfr[fn][1] = *reinterpret_cast<const unsigned*>(bs + n * BK + g1 * 8 + tig * 2);
            }
            #pragma unroll
            for (int fm = 0; fm < FM; fm++)
                #pragma unroll
                for (int fn = 0; fn < 4; fn++)
                    MMA_F16(acc[fm][fn], af[fm], bfr[fn]);
        }
    }

    #pragma unroll
    for (int fm = 0; fm < FM; fm++) {
        #pragma unroll
        for (int fn = 0; fn < 4; fn++) {
            int m0 = bm + wm + fm * 16 + grp;
            int n  = bn + wn + fn * 8 + tig * 2;
            #pragma unroll
            for (int half = 0; half < 2; half++) {
                int m = m0 + half * 8;
                float x0 = acc[fm][fn][half * 2 + 0] * alpha;
                float x1 = acc[fm][fn][half * 2 + 1] * alpha;
                if (bias) { x0 += bias[n]; x1 += bias[n + 1]; }
                if (act == ACT_RELU) {
                    x0 = fmaxf(x0, 0.0f); x1 = fmaxf(x1, 0.0f);
                } else if (act == ACT_SIGMOID) {
                    x0 = 1.0f / (1.0f + __expf(-x0));
                    x1 = 1.0f / (1.0f + __expf(-x1));
                }
                if (mode == 2) {
                    hf* Cb = (hf*)Cv;
                    *reinterpret_cast<__half2*>(&Cb[(size_t)m * N + n]) =
                        __floats2half2_rn(x0, x1);
                } else {
                    float* Cf = (float*)Cv;
                    if (residual) {
                        float2 r = *reinterpret_cast<const float2*>(&residual[(size_t)m * N + n]);
                        x0 += r.x; x1 += r.y;
                    }
                    if (mode == 1) { x0 = to_tf32(x0); x1 = to_tf32(x1); }
                    *reinterpret_cast<float2*>(&Cf[(size_t)m * N + n]) = make_float2(x0, x1);
                }
            }
        }
    }
}

// ---------------- flash attention: fp16 QK^T (m16n8k16), tf32 PV ----------------
// smem bytes: Qs hf[64][72] | Ks hf[2][64][72] | Vs f32[2][64][56] | Ms f32[2][64][68]
#define HP 72
#define VS_PITCH 56
#define MS_PITCH 68
#define FLB_QS 0
#define FLB_KS 9216
#define FLB_VS 27648
#define FLB_MS 56320
#define FLB_TOTAL 91136

__global__ __launch_bounds__(128) void flash_kernel(
    const hf* __restrict__ q, const hf* __restrict__ k,
    const float* __restrict__ v, const float* __restrict__ mask,
    float* __restrict__ po, float* __restrict__ pm, float* __restrict__ pl) {
    extern __shared__ char smc[];
    hf* Qs = reinterpret_cast<hf*>(smc + FLB_QS);
    int t = threadIdx.x;
    int wid = t >> 5, lane = t & 31, grp = lane >> 2, tig = lane & 3;
    int t0 = blockIdx.x * 64;
    int h  = blockIdx.y;
    int rsp = blockIdx.z;
    int rbase = rsp * (N_RES / RSPLIT);
    int wr = wid * 16;

    // load Q (fp16, pre-scaled): 64 rows x 6 granules of 16B
    for (int i = t; i < 64 * 6; i += 128) {
        int r = i / 6, f = i % 6;
        *reinterpret_cast<uint4*>(&Qs[r * HP + f * 8]) =
            *reinterpret_cast<const uint4*>(&q[(size_t)(t0 + r) * C_DIM + h * KD + f * 8]);
    }

    const int NCH = (N_RES / RSPLIT) / RCHUNK;

    auto issue = [&](int ch, int b) {
        int r0 = rbase + ch * RCHUNK;
        hf*    ks = reinterpret_cast<hf*>(smc + FLB_KS) + b * 64 * HP;
        float* vs = reinterpret_cast<float*>(smc + FLB_VS) + b * 64 * VS_PITCH;
        float* ms = reinterpret_cast<float*>(smc + FLB_MS) + b * 64 * MS_PITCH;
        for (int i = t; i < 64 * 6; i += 128) {
            int r = i / 6, f = i % 6;
            cp16(&ks[r * HP + f * 8], &k[(size_t)(r0 + r) * C_DIM + h * KD + f * 8]);
        }
        for (int i = t; i < 64 * 12; i += 128) {
            int r = i / 12, f = i % 12;
            cp16(&vs[r * VS_PITCH + f * 4], &v[(size_t)(r0 + r) * C_DIM + h * KD + f * 4]);
        }
        for (int i = t; i < 64 * 16; i += 128) {
            int rr = i / 16, f = i % 16;
            cp16(&ms[rr * MS_PITCH + f * 4],
                 &mask[((size_t)h * T_TOK + t0 + rr) * N_RES + r0 + f * 4]);
        }
    };

    issue(0, 0); CP_COMMIT();
    issue(1, 1); CP_COMMIT();

    float m_lo = -1e30f, m_hi = -1e30f, l_lo = 0.0f, l_hi = 0.0f;
    float acc_o[6][4];
    #pragma unroll
    for (int i = 0; i < 6; i++)
        #pragma unroll
        for (int e = 0; e < 4; e++) acc_o[i][e] = 0.0f;

    for (int ch = 0; ch < NCH; ch++) {
        int b = ch & 1;
        CP_WAIT(1);
        __syncthreads();
        hf*    ks = reinterpret_cast<hf*>(smc + FLB_KS) + b * 64 * HP;
        float* vs = reinterpret_cast<float*>(smc + FLB_VS) + b * 64 * VS_PITCH;
        float* ms = reinterpret_cast<float*>(smc + FLB_MS) + b * 64 * MS_PITCH;

        // S = Q @ K^T : 3 fp16 k16-steps
        float acc_s[8][4];
        #pragma unroll
        for (int fn = 0; fn < 8; fn++)
            #pragma unroll
            for (int e = 0; e < 4; e++) acc_s[fn][e] = 0.0f;
        #pragma unroll
        for (int s = 0; s < 3; s++) {
            int k0 = s * 16;
            unsigned a[4];
            a[0] = *reinterpret_cast<const unsigned*>(Qs + (wr + grp) * HP + k0 + 2 * tig);
            a[1] = *reinterpret_cast<const unsigned*>(Qs + (wr + grp + 8) * HP + k0 + 2 * tig);
            a[2] = *reinterpret_cast<const unsigned*>(Qs + (wr + grp) * HP + k0 + 8 + 2 * tig);
            a[3] = *reinterpret_cast<const unsigned*>(Qs + (wr + grp + 8) * HP + k0 + 8 + 2 * tig);
            #pragma unroll
            for (int fn = 0; fn < 8; fn++) {
                unsigned bb[2];
                bb[0] = *reinterpret_cast<const unsigned*>(ks + (fn * 8 + grp) * HP + k0 + 2 * tig);
                bb[1] = *reinterpret_cast<const unsigned*>(ks + (fn * 8 + grp) * HP + k0 + 8 + 2 * tig);
                MMA_F16(acc_s[fn], a, bb);
            }
        }
        float mx_lo = -1e30f, mx_hi = -1e30f;
        #pragma unroll
        for (int fn = 0; fn < 8; fn++) {
            int col = fn * 8 + 2 * tig;
            float2 blo = *reinterpret_cast<float2*>(&ms[(wr + grp) * MS_PITCH + col]);
            float2 bhi = *reinterpret_cast<float2*>(&ms[(wr + grp + 8) * MS_PITCH + col]);
            acc_s[fn][0] += BIGF * (blo.x - 1.0f);
            acc_s[fn][1] += BIGF * (blo.y - 1.0f);
            acc_s[fn][2] += BIGF * (bhi.x - 1.0f);
            acc_s[fn][3] += BIGF * (bhi.y - 1.0f);
            mx_lo = fmaxf(mx_lo, fmaxf(acc_s[fn][0], acc_s[fn][1]));
            mx_hi = fmaxf(mx_hi, fmaxf(acc_s[fn][2], acc_s[fn][3]));
        }
        mx_lo = fmaxf(mx_lo, __shfl_xor_sync(0xffffffffu, mx_lo, 1));
        mx_lo = fmaxf(mx_lo, __shfl_xor_sync(0xffffffffu, mx_lo, 2));
        mx_hi = fmaxf(mx_hi, __shfl_xor_sync(0xffffffffu, mx_hi, 1));
        mx_hi = fmaxf(mx_hi, __shfl_xor_sync(0xffffffffu, mx_hi, 2));
        float mn_lo = fmaxf(m_lo, mx_lo), mn_hi = fmaxf(m_hi, mx_hi);
        float sc_lo = __expf(m_lo - mn_lo), sc_hi = __expf(m_hi - mn_hi);
        m_lo = mn_lo; m_hi = mn_hi;
        float rs_lo = 0.0f, rs_hi = 0.0f;
        #pragma unroll
        for (int fn = 0; fn < 8; fn++) {
            int col = fn * 8 + 2 * tig;
            float p0 = __expf(acc_s[fn][0] - mn_lo);
            float p1 = __expf(acc_s[fn][1] - mn_lo);
            float p2 = __expf(acc_s[fn][2] - mn_hi);
            float p3 = __expf(acc_s[fn][3] - mn_hi);
            rs_lo += p0 + p1; rs_hi += p2 + p3;
            *reinterpret_cast<float2*>(&ms[(wr + grp) * MS_PITCH + col]) =
                make_float2(to_tf32(p0), to_tf32(p1));
            *reinterpret_cast<float2*>(&ms[(wr + grp + 8) * MS_PITCH + col]) =
                make_float2(to_tf32(p2), to_tf32(p3));
        }
        rs_lo += __shfl_xor_sync(0xffffffffu, rs_lo, 1);
        rs_lo += __shfl_xor_sync(0xffffffffu, rs_lo, 2);
        rs_hi += __shfl_xor_sync(0xffffffffu, rs_hi, 1);
        rs_hi += __shfl_xor_sync(0xffffffffu, rs_hi, 2);
        l_lo = l_lo * sc_lo + rs_lo;
        l_hi = l_hi * sc_hi + rs_hi;
        #pragma unroll
        for (int fn = 0; fn < 6; fn++) {
            acc_o[fn][0] *= sc_lo; acc_o[fn][1] *= sc_lo;
            acc_o[fn][2] *= sc_hi; acc_o[fn][3] *= sc_hi;
        }
        __syncwarp();
        // O += P @ V : 8 tf32 k8-steps
        #pragma unroll
        for (int s = 0; s < 8; s++) {
            int k0 = s * 8;
            unsigned a[4];
            a[0] = __float_as_uint(ms[(wr + grp) * MS_PITCH + k0 + tig]);
            a[1] = __float_as_uint(ms[(wr + grp + 8) * MS_PITCH + k0 + tig]);
            a[2] = __float_as_uint(ms[(wr + grp) * MS_PITCH + k0 + 4 + tig]);
            a[3] = __float_as_uint(ms[(wr + grp + 8) * MS_PITCH + k0 + 4 + tig]);
            #pragma unroll
            for (int fn = 0; fn < 6; fn++) {
                unsigned bb[2];
                bb[0] = __float_as_uint(vs[(k0 + tig) * VS_PITCH + fn * 8 + grp]);
                bb[1] = __float_as_uint(vs[(k0 + 4 + tig) * VS_PITCH + fn * 8 + grp]);
                MMA_TF32(acc_o[fn], a, bb);
            }
        }
        __syncthreads();
        if (ch + 2 < NCH) issue(ch + 2, b);
        CP_COMMIT();
    }

    int row_lo = (rsp * H_HEADS + h) * T_TOK + t0 + wr + grp;
    int row_hi = row_lo + 8;
    #pragma unroll
    for (int fn = 0; fn < 6; fn++) {
        int c = fn * 8 + 2 * tig;
        *reinterpret_cast<float2*>(&po[(size_t)row_lo * KD + c]) =
            make_float2(acc_o[fn][0], acc_o[fn][1]);
        *reinterpret_cast<float2*>(&po[(size_t)row_hi * KD + c]) =
            make_float2(acc_o[fn][2], acc_o[fn][3]);
    }
    if (tig == 0) {
        pm[row_lo] = m_lo; pm[row_hi] = m_hi;
        pl[row_lo] = l_lo; pl[row_hi] = l_hi;
    }
}

// ---------------- combine r-splits, apply gate, write wag fp16 ----------------
__global__ void combine_kernel(const float* __restrict__ po, const float* __restrict__ pm,
                               const float* __restrict__ pl, const float* __restrict__ gate,
                               hf* __restrict__ wag) {
    int idx = blockIdx.x * 256 + threadIdx.x;
    const int TOT = H_HEADS * T_TOK * KD;
    const int HT  = H_HEADS * T_TOK;
    if (idx >= TOT) return;
    int c  = idx % KD;
    int ht = idx / KD;
    int tt = ht % T_TOK, h = ht / T_TOK;
    float mm = -1e30f;
    #pragma unroll
    for (int r = 0; r < RSPLIT; r++) mm = fmaxf(mm, pm[r * HT + ht]);
    float l = 0.0f, o = 0.0f;
    #pragma unroll
    for (int r = 0; r < RSPLIT; r++) {
        float s = __expf(pm[r * HT + ht] - mm);
        l += pl[r * HT + ht] * s;
        o += po[(size_t)r * TOT + idx] * s;
    }
    o /= l;
    float g = gate[(size_t)tt * C_DIM + h * KD + c];
    wag[(size_t)tt * C_DIM + h * KD + c] = __float2half_rn(o * g);
}

// ---------------- host launch ----------------
static void* symv(const void* s) {
    void* p = nullptr;
    cudaGetSymbolAddress(&p, s);
    return p;
}

extern "C" void kernel_launch(void* const* d_in, const int* in_sizes, int n_in,
                              void* d_out, int out_size) {
    const float* original   = (const float*)d_in[0];
    const float* resampled  = (const float*)d_in[1];
    const float* attn_mask  = (const float*)d_in[2];
    const float* qn_scale   = (const float*)d_in[5];
    const float* qn_offset  = (const float*)d_in[6];
    const float* dn_scale   = (const float*)d_in[7];
    const float* dn_offset  = (const float*)d_in[8];
    const float* query_w    = (const float*)d_in[9];
    const float* key_w      = (const float*)d_in[10];
    const float* value_w    = (const float*)d_in[11];
    const float* gating_w   = (const float*)d_in[12];
    const float* gating_b   = (const float*)d_in[13];
    const float* output_w   = (const float*)d_in[14];
    const float* output_b   = (const float*)d_in[15];
    const float* rt_ln_scale  = (const float*)d_in[16];
    const float* rt_ln_offset = (const float*)d_in[17];
    const float* rt_w1 = (const float*)d_in[18];
    const float* rt_b1 = (const float*)d_in[19];
    const float* rt_w2 = (const float*)d_in[20];
    const float* rt_b2 = (const float*)d_in[21];
    const float* ot_ln_scale  = (const float*)d_in[22];
    const float* ot_ln_offset = (const float*)d_in[23];
    const float* ot_w1 = (const float*)d_in[24];
    const float* ot_b1 = (const float*)d_in[25];
    const float* ot_w2 = (const float*)d_in[26];
    const float* ot_b2 = (const float*)d_in[27];

    float* out_res  = (float*)d_out;
    float* out_orig = out_res + (size_t)T_TOK * C_DIM;

    hf*    p_qin  = (hf*)symv(g_qin);
    hf*    p_din  = (hf*)symv(g_din);
    hf*    p_ln4  = (hf*)symv(g_ln4);
    hf*    p_qh   = (hf*)symv(g_qh);
    hf*    p_kh   = (hf*)symv(g_kh);
    float* p_gate = (float*)symv(g_gate);
    float* p_v    = (float*)symv(g_v);
    hf*    p_wag  = (hf*)symv(g_wag);
    hf*    p_ln3  = (hf*)symv(g_ln3);
    hf*    p_h1   = (hf*)symv(g_h1);
    hf*    p_h2   = (hf*)symv(g_h2);
    hf*    p_wts  = (hf*)symv(g_wts);
    float* p_po   = (float*)symv(g_po);
    float* p_pm   = (float*)symv(g_pm);
    float* p_pl   = (float*)symv(g_pl);

    const int smem128 = STAGES * (128 * BK + 128 * BK) * 2;   // 65536 B
    const int smem64  = STAGES * (64 * BK + 128 * BK) * 2;    // 49152 B
    const int flash_smem = FLB_TOTAL;                         // 91136 B
    cudaFuncSetAttribute(gemm_hf<128>, cudaFuncAttributeMaxDynamicSharedMemorySize, smem128);
    cudaFuncSetAttribute(gemm_hf<64>,  cudaFuncAttributeMaxDynamicSharedMemorySize, smem64);
    cudaFuncSetAttribute(flash_kernel, cudaFuncAttributeMaxDynamicSharedMemorySize, flash_smem);

    const float inv_sqrt_kd = 0.14433756729740643f;
    const int BIG_HALF = 1 << 30;

    cudaStream_t s2 = 0;
    cudaEvent_t ev_root = 0, ev_ln = 0, ev_w = 0, ev_ot = 0;
    cudaStreamCreateWithFlags(&s2, cudaStreamNonBlocking);
    cudaEventCreateWithFlags(&ev_root, cudaEventDisableTiming);
    cudaEventCreateWithFlags(&ev_ln, cudaEventDisableTiming);
    cudaEventCreateWithFlags(&ev_w,  cudaEventDisableTiming);
    cudaEventCreateWithFlags(&ev_ot, cudaEventDisableTiming);
    bool fork_ok = s2 && ev_root && ev_ln && ev_w && ev_ot;

    SrcPtrs sp;
    sp.p[0] = query_w;  sp.p[1] = key_w;  sp.p[2] = value_w;
    sp.p[3] = gating_w; sp.p[4] = output_w;
    sp.p[5] = rt_w1;    sp.p[6] = rt_w2;  sp.p[7] = ot_w1; sp.p[8] = ot_w2;

    if (fork_ok) {
        cudaEventRecord(ev_root, 0);
        cudaStreamWaitEvent(s2, ev_root, 0);

        wt_kernel<<<3024, 256, 0, s2>>>(sp, p_wts);
        cudaEventRecord(ev_w, s2);

        ln_fused_kernel<<<T_TOK + 2 * N_RES, 128>>>(resampled, original,
            qn_scale, qn_offset, dn_scale, dn_offset, ot_ln_scale, ot_ln_offset,
            p_qin, p_din, p_ln4);
        cudaEventRecord(ev_ln, 0);

        cudaStreamWaitEvent(s2, ev_ln, 0);
        gemm_hf<128><<<dim3(12, 32), 256, smem128, s2>>>(p_ln4,
            p_wts + OFF_OT1, p_h2, 1.0f, ot_b1, ACT_RELU, nullptr, 2,
            nullptr, nullptr, 0.0f, nullptr, 0, nullptr, 0,
            N_RES, F_DIM, C_DIM, BIG_HALF);
        gemm_hf<64><<<dim3(3, 64), 256, smem64, s2>>>(p_h2,
            p_wts + OFF_OT2, out_orig, 1.0f, ot_b2, ACT_NONE, original, 0,
            nullptr, nullptr, 0.0f, nullptr, 0, nullptr, 0,
            N_RES, C_DIM, F_DIM, BIG_HALF);
        cudaEventRecord(ev_ot, s2);

        cudaStreamWaitEvent(0, ev_w, 0);
    } else {
        wt_kernel<<<3024, 256>>>(sp, p_wts);
        ln_fused_kernel<<<T_TOK + 2 * N_RES, 128>>>(resampled, original,
            qn_scale, qn_offset, dn_scale, dn_offset, ot_ln_scale, ot_ln_offset,
            p_qin, p_din, p_ln4);
        gemm_hf<128><<<dim3(12, 32), 256, smem128>>>(p_ln4,
            p_wts + OFF_OT1, p_h2, 1.0f, ot_b1, ACT_RELU, nullptr, 2,
            nullptr, nullptr, 0.0f, nullptr, 0, nullptr, 0,
            N_RES, F_DIM, C_DIM, BIG_HALF);
        gemm_hf<64><<<dim3(3, 64), 256, smem64>>>(p_h2,
            p_wts + OFF_OT2, out_orig, 1.0f, ot_b2, ACT_NONE, original, 0,
            nullptr, nullptr, 0.0f, nullptr, 0, nullptr, 0,
            N_RES, C_DIM, F_DIM, BIG_HALF);
    }

    // main chain: q (fp16) + gate (f32); k (fp16) + v (f32 tf32)
    gemm_hf<64><<<dim3(6, 8), 256, smem64>>>(p_qin,
        p_wts + OFF_QW, p_qh, inv_sqrt_kd, nullptr, ACT_NONE, nullptr, 2,
        p_wts + OFF_GW, p_gate, 1.0f, gating_b, ACT_SIGMOID, nullptr, 0,
        T_TOK, C_DIM, C_DIM, 3);
    gemm_hf<128><<<dim3(6, 32), 256, smem128>>>(p_din,
        p_wts + OFF_KW, p_kh, 1.0f, nullptr, ACT_NONE, nullptr, 2,
        p_wts + OFF_VW, p_v, 1.0f, nullptr, ACT_NONE, nullptr, 1,
        N_RES, C_DIM, C_DIM, 3);

    flash_kernel<<<dim3(T_TOK / 64, H_HEADS, RSPLIT), 128, flash_smem>>>(
        p_qh, p_kh, p_v, attn_mask, p_po, p_pm, p_pl);
    combine_kernel<<<(H_HEADS * T_TOK * KD + 255) / 256, 256>>>(p_po, p_pm, p_pl, p_gate, p_wag);

    gemm_hf<64><<<dim3(3, 8), 256, smem64>>>(p_wag,
        p_wts + OFF_OW, out_res, 1.0f, output_b, ACT_NONE, resampled, 0,
        nullptr, nullptr, 0.0f, nullptr, 0, nullptr, 0,
        T_TOK, C_DIM, C_DIM, BIG_HALF);

    ln_kernel<<<T_TOK, 128>>>(out_res, rt_ln_scale, rt_ln_offset, p_ln3);
    gemm_hf<64><<<dim3(12, 8), 256, smem64>>>(p_ln3,
        p_wts + OFF_RT1, p_h1, 1.0f, rt_b1, ACT_RELU, nullptr, 2,
        nullptr, nullptr, 0.0f, nullptr, 0, nullptr, 0,
        T_TOK, F_DIM, C_DIM, BIG_HALF);
    gemm_hf<64><<<dim3(3, 8), 256, smem64>>>(p_h1,
        p_wts + OFF_RT2, out_res, 1.0f, rt_b2, ACT_NONE, out_res, 0,
        nullptr, nullptr, 0.0f, nullptr, 0, nullptr, 0,
        T_TOK, C_DIM, F_DIM, BIG_HALF);

    if (fork_ok) cudaStreamWaitEvent(0, ev_ot, 0);
}

// round 16
// speedup vs baseline: 1.7843x; 1.0950x over previous
#include <cuda_runtime.h>
#include <cuda_fp16.h>
#include <math.h>

#define T_TOK 512
#define N_RES 4096
#define C_DIM 384
#define H_HEADS 8
#define KD 48
#define F_DIM 1536
#define LN_EPS 1e-5f
#define BIGF 1e9f
#define RSPLIT 4
#define RCHUNK 64
#define STAGES 4
#define BK 32

typedef __half hf;

// ---------------- scratch (device globals) ----------------
__device__ hf    g_qin [T_TOK * C_DIM];
__device__ hf    g_din [N_RES * C_DIM];
__device__ hf    g_ln4 [N_RES * C_DIM];
__device__ hf    g_qh  [T_TOK * C_DIM];      // fp16 q (pre-scaled)
__device__ hf    g_kh  [N_RES * C_DIM];      // fp16 k
__device__ hf    g_vt  [C_DIM * N_RES];      // fp16 V^T [c][r]
__device__ float g_gate[T_TOK * C_DIM];
__device__ hf    g_wag [T_TOK * C_DIM];
__device__ hf    g_ln3 [T_TOK * C_DIM];
__device__ hf    g_h1  [T_TOK * F_DIM];
__device__ hf    g_h2  [N_RES * F_DIM];
__device__ float g_part[N_RES * C_DIM];      // ot2 split-K partial
// fp16 TRANSPOSED weights Wt[N][K] (element offsets)
#define OFF_QW  0
#define OFF_KW  147456
#define OFF_VW  294912
#define OFF_GW  442368
#define OFF_OW  589824
#define OFF_RT1 737280
#define OFF_RT2 1327104
#define OFF_OT1 1916928
#define OFF_OT2 2506752
#define WTS_TOTAL 3096576
__device__ hf g_wts[WTS_TOTAL];
// flash partials
__device__ float g_po[RSPLIT * H_HEADS * T_TOK * KD];
__device__ float g_pm[RSPLIT * H_HEADS * T_TOK];
__device__ float g_pl[RSPLIT * H_HEADS * T_TOK];

__device__ __forceinline__ float to_tf32(float x) {
    asm("cvt.rna.tf32.f32 %0, %1;" : "=f"(x) : "f"(x));
    return x;
}

#define MMA_F16(c, a, b) \
    asm volatile("mma.sync.aligned.m16n8k16.row.col.f32.f16.f16.f32 " \
        "{%0,%1,%2,%3}, {%4,%5,%6,%7}, {%8,%9}, {%0,%1,%2,%3};" \
        : "+f"((c)[0]), "+f"((c)[1]), "+f"((c)[2]), "+f"((c)[3]) \
        : "r"((a)[0]), "r"((a)[1]), "r"((a)[2]), "r"((a)[3]), \
          "r"((b)[0]), "r"((b)[1]))

__device__ __forceinline__ void cp16(void* dst, const void* src) {
    unsigned d = (unsigned)__cvta_generic_to_shared(dst);
    asm volatile("cp.async.ca.shared.global [%0], [%1], 16;" :: "r"(d), "l"(src));
}
#define CP_COMMIT() asm volatile("cp.async.commit_group;")
#define CP_WAIT(n)  asm volatile("cp.async.wait_group %0;" :: "n"(n))

// ---------------- weight transpose + fp16 convert ----------------
struct SrcPtrs { const float* p[9]; };

__global__ __launch_bounds__(256) void wt_kernel(SrcPtrs s, hf* __restrict__ dst) {
    const int segK[9]   = {384, 384, 384, 384, 384, 384, 1536, 384, 1536};
    const int segN[9]   = {384, 384, 384, 384, 384, 1536, 384, 1536, 384};
    const int segOff[9] = {OFF_QW, OFF_KW, OFF_VW, OFF_GW, OFF_OW, OFF_RT1, OFF_RT2, OFF_OT1, OFF_OT2};
    const int cum[10]   = {0, 144, 288, 432, 576, 720, 1296, 1872, 2448, 3024};
    int b = blockIdx.x;
    int seg = 0;
    #pragma unroll
    for (int i = 1; i < 9; i++) if (b >= cum[i]) seg = i;
    int tile = b - cum[seg];
    int K = segK[seg], N = segN[seg];
    int ntn = N >> 5;
    int k0 = (tile / ntn) * 32, n0 = (tile % ntn) * 32;
    const float* src = s.p[seg];

    __shared__ float smt[32][33];
    int t = threadIdx.x;
    int r = t >> 3, c4 = (t & 7) * 4;
    float4 v = *reinterpret_cast<const float4*>(&src[(size_t)(k0 + r) * N + n0 + c4]);
    smt[r][c4 + 0] = v.x; smt[r][c4 + 1] = v.y;
    smt[r][c4 + 2] = v.z; smt[r][c4 + 3] = v.w;
    __syncthreads();
    int n = t >> 3, k4 = (t & 7) * 4;
    __half2 lo = __floats2half2_rn(smt[k4 + 0][n], smt[k4 + 1][n]);
    __half2 hi = __floats2half2_rn(smt[k4 + 2][n], smt[k4 + 3][n]);
    hf* d = dst + segOff[seg] + (size_t)(n0 + n) * K + k0 + k4;
    *reinterpret_cast<__half2*>(d)     = lo;
    *reinterpret_cast<__half2*>(d + 2) = hi;
}

// ---------------- LayerNorm ----------------
__device__ __forceinline__ void ln_row(const float* __restrict__ xr,
                                       const float* __restrict__ scale,
                                       const float* __restrict__ offset,
                                       hf* __restrict__ orow) {
    int t = threadIdx.x;
    float v0 = xr[t], v1 = xr[t + 128], v2 = xr[t + 256];
    float s  = v0 + v1 + v2;
    float s2 = v0 * v0 + v1 * v1 + v2 * v2;
    #pragma unroll
    for (int o = 16; o; o >>= 1) {
        s  += __shfl_down_sync(0xffffffffu, s,  o);
        s2 += __shfl_down_sync(0xffffffffu, s2, o);
    }
    __shared__ float sh[8];
    __shared__ float mu_s, rstd_s;
    int wid = t >> 5, lane = t & 31;
    if (lane == 0) { sh[wid] = s; sh[4 + wid] = s2; }
    __syncthreads();
    if (t == 0) {
        float ts  = sh[0] + sh[1] + sh[2] + sh[3];
        float ts2 = sh[4] + sh[5] + sh[6] + sh[7];
        float mu  = ts * (1.0f / C_DIM);
        float var = ts2 * (1.0f / C_DIM) - mu * mu;
        mu_s = mu; rstd_s = rsqrtf(var + LN_EPS);
    }
    __syncthreads();
    float mu = mu_s, rstd = rstd_s;
    orow[t]       = __float2half_rn(scale[t]       * (v0 - mu) * rstd + offset[t]);
    orow[t + 128] = __float2half_rn(scale[t + 128] * (v1 - mu) * rstd + offset[t + 128]);
    orow[t + 256] = __float2half_rn(scale[t + 256] * (v2 - mu) * rstd + offset[t + 256]);
}

__global__ void ln_kernel(const float* __restrict__ x, const float* __restrict__ scale,
                          const float* __restrict__ offset, hf* __restrict__ out) {
    int row = blockIdx.x;
    ln_row(x + (size_t)row * C_DIM, scale, offset, out + (size_t)row * C_DIM);
}

__global__ void ln_fused_kernel(const float* __restrict__ resampled, const float* __restrict__ original,
                                const float* __restrict__ qn_s, const float* __restrict__ qn_o,
                                const float* __restrict__ dn_s, const float* __restrict__ dn_o,
                                const float* __restrict__ ot_s, const float* __restrict__ ot_o,
                                hf* __restrict__ qin, hf* __restrict__ din, hf* __restrict__ ln4) {
    int row = blockIdx.x;
    if (row < T_TOK) {
        ln_row(resampled + (size_t)row * C_DIM, qn_s, qn_o, qin + (size_t)row * C_DIM);
    } else if (row < T_TOK + N_RES) {
        int r = row - T_TOK;
        ln_row(original + (size_t)r * C_DIM, dn_s, dn_o, din + (size_t)r * C_DIM);
    } else {
        int r = row - T_TOK - N_RES;
        ln_row(original + (size_t)r * C_DIM, ot_s, ot_o, ln4 + (size_t)r * C_DIM);
    }
}

// ---------------- elementwise add (split-K merge) ----------------
__global__ void add_kernel(float* __restrict__ dst, const float* __restrict__ src, int n4) {
    int i = blockIdx.x * 256 + threadIdx.x;
    if (i < n4) {
        float4 a = reinterpret_cast<float4*>(dst)[i];
        float4 b = reinterpret_cast<const float4*>(src)[i];
        reinterpret_cast<float4*>(dst)[i] =
            make_float4(a.x + b.x, a.y + b.y, a.z + b.z, a.w + b.w);
    }
}

// ---------------- MTx128xBK fp16 GEMM, 4-stage cp.async, m16n8k16 ----------------
// A[M][K-stride] fp16 (iterate Klen), B = Wt[N][K-stride] fp16.
// modes: 0=f32(+res), 1=f32 tf32-rounded(+res), 2=fp16, 4=fp16 TRANSPOSED (C[n][m], stride M)
#define ACT_NONE 0
#define ACT_RELU 1
#define ACT_SIGMOID 2

template<int MT>
__global__ __launch_bounds__(256, 2) void gemm_hf(
    const hf* __restrict__ A0,
    const hf* __restrict__ B0, void* __restrict__ C0v, float alpha0,
    const float* __restrict__ bias0, int act0, const float* __restrict__ res0, int mode0,
    const hf* __restrict__ A1,
    const hf* __restrict__ B1, void* __restrict__ C1v, float alpha1,
    const float* __restrict__ bias1, int act1, const float* __restrict__ res1, int mode1,
    int M, int N, int K, int Klen, int halfX) {
    constexpr int A_STAGE = MT * BK;
    constexpr int B_STAGE = 128 * BK;
    constexpr int FM = MT / 32;
    constexpr int AG = MT / 64;
    extern __shared__ hf smg[];
    hf* As = smg;
    hf* Bs = smg + STAGES * A_STAGE;

    int t = threadIdx.x;
    int bxx = blockIdx.x;
    const hf* A = A0; const hf* B = B0; void* Cv = C0v; float alpha = alpha0;
    const float* bias = bias0; int act = act0; const float* residual = res0; int mode = mode0;
    if (bxx >= halfX) {
        bxx -= halfX;
        A = A1; B = B1; Cv = C1v; alpha = alpha1; bias = bias1; act = act1; residual = res1; mode = mode1;
    }
    int bm = blockIdx.y * MT, bn = bxx * 128;
    int wid = t >> 5, lane = t & 31, grp = lane >> 2, tig = lane & 3;
    int wm = (wid >> 2) * (MT / 2);
    int wn = (wid & 3) * 32;

    int a_dst[AG]; size_t a_src[AG];
    #pragma unroll
    for (int i = 0; i < AG; i++) {
        int idx = t + i * 256;
        int m = idx >> 2, g = idx & 3;
        a_dst[i] = (m * 4 + (g ^ ((m >> 1) & 3))) * 8;
        a_src[i] = (size_t)(bm + m) * K + g * 8;
    }
    int b_dst[2]; size_t b_src[2];
    #pragma unroll
    for (int i = 0; i < 2; i++) {
        int idx = t + i * 256;
        int n = idx >> 2, g = idx & 3;
        b_dst[i] = (n * 4 + (g ^ ((n >> 1) & 3))) * 8;
        b_src[i] = (size_t)(bn + n) * K + g * 8;
    }

    float acc[FM][4][4];
    #pragma unroll
    for (int i = 0; i < FM; i++)
        #pragma unroll
        for (int j = 0; j < 4; j++)
            #pragma unroll
            for (int r = 0; r < 4; r++) acc[i][j][r] = 0.0f;

    int kTiles = Klen / BK;

    #pragma unroll
    for (int pt = 0; pt < STAGES - 1; pt++) {
        hf* ab = As + pt * A_STAGE;
        hf* bb = Bs + pt * B_STAGE;
        #pragma unroll
        for (int i = 0; i < AG; i++) cp16(ab + a_dst[i], A + a_src[i] + pt * BK);
        #pragma unroll
        for (int i = 0; i < 2; i++)  cp16(bb + b_dst[i], B + b_src[i] + pt * BK);
        CP_COMMIT();
    }

    for (int kt = 0; kt < kTiles; kt++) {
        CP_WAIT(STAGES - 2);
        __syncthreads();
        int nt = kt + STAGES - 1;
        if (nt < kTiles) {
            int buf = nt % STAGES;
            hf* ab = As + buf * A_STAGE;
            hf* bb = Bs + buf * B_STAGE;
            #pragma unroll
            for (int i = 0; i < AG; i++) cp16(ab + a_dst[i], A + a_src[i] + nt * BK);
            #pragma unroll
            for (int i = 0; i < 2; i++)  cp16(bb + b_dst[i], B + b_src[i] + nt * BK);
        }
        CP_COMMIT();
        const hf* as = As + (kt % STAGES) * A_STAGE;
        const hf* bs = Bs + (kt % STAGES) * B_STAGE;
        #pragma unroll
        for (int s = 0; s < 2; s++) {
            unsigned af[FM][4];
            #pragma unroll
            for (int fm = 0; fm < FM; fm++) {
                int m = wm + fm * 16 + grp;
                int sw = (m >> 1) & 3;
                int g0 = (2 * s) ^ sw, g1 = (2 * s + 1) ^ sw;
                af[fm][0] = *reinterpret_cast<const unsigned*>(as + m * BK + g0 * 8 + tig * 2);
                af[fm][1] = *reinterpret_cast<const unsigned*>(as + (m + 8) * BK + g0 * 8 + tig * 2);
                af[fm][2] = *reinterpret_cast<const unsigned*>(as + m * BK + g1 * 8 + tig * 2);
                af[fm][3] = *reinterpret_cast<const unsigned*>(as + (m + 8) * BK + g1 * 8 + tig * 2);
            }
            unsigned bfr[4][2];
            #pragma unroll
            for (int fn = 0; fn < 4; fn++) {
                int n = wn + fn * 8 + grp;
                int sw = (n >> 1) & 3;
                int g0 = (2 * s) ^ sw, g1 = (2 * s + 1) ^ sw;
                bfr[fn][0] = *reinterpret_cast<const unsigned*>(bs + n * BK + g0 * 8 + tig * 2);
                bfr[fn][1] = *reinterpret_cast<const unsigned*>(bs + n * BK + g1 * 8 + tig * 2);
            }
            #pragma unroll
            for (int fm = 0; fm < FM; fm++)
                #pragma unroll
                for (int fn = 0; fn < 4; fn++)
                    MMA_F16(acc[fm][fn], af[fm], bfr[fn]);
        }
    }

    #pragma unroll
    for (int fm = 0; fm < FM; fm++) {
        #pragma unroll
        for (int fn = 0; fn < 4; fn++) {
            int m0 = bm + wm + fm * 16 + grp;
            int n  = bn + wn + fn * 8 + tig * 2;
            #pragma unroll
            for (int half = 0; half < 2; half++) {
                int m = m0 + half * 8;
                float x0 = acc[fm][fn][half * 2 + 0] * alpha;
                float x1 = acc[fm][fn][half * 2 + 1] * alpha;
                if (bias) { x0 += bias[n]; x1 += bias[n + 1]; }
                if (act == ACT_RELU) {
                    x0 = fmaxf(x0, 0.0f); x1 = fmaxf(x1, 0.0f);
                } else if (act == ACT_SIGMOID) {
                    x0 = 1.0f / (1.0f + __expf(-x0));
                    x1 = 1.0f / (1.0f + __expf(-x1));
                }
                if (mode == 2) {
                    hf* Cb = (hf*)Cv;
                    *reinterpret_cast<__half2*>(&Cb[(size_t)m * N + n]) =
                        __floats2half2_rn(x0, x1);
                } else if (mode == 4) {
                    hf* Cb = (hf*)Cv;
                    Cb[(size_t)n * M + m]       = __float2half_rn(x0);
                    Cb[(size_t)(n + 1) * M + m] = __float2half_rn(x1);
                } else {
                    float* Cf = (float*)Cv;
                    if (residual) {
                        float2 r = *reinterpret_cast<const float2*>(&residual[(size_t)m * N + n]);
                        x0 += r.x; x1 += r.y;
                    }
                    if (mode == 1) { x0 = to_tf32(x0); x1 = to_tf32(x1); }
                    *reinterpret_cast<float2*>(&Cf[(size_t)m * N + n]) = make_float2(x0, x1);
                }
            }
        }
    }
}

// ---------------- flash attention: fp16 QK^T and fp16 PV ----------------
// smem bytes: Qs hf[64][72] | Ks hf[2][64][72] | Vt hf[2][48][72] | Ms f32[2][64][68] | Ps hf[64][72]
#define HP 72
#define MS_PITCH 68
#define FLB_QS 0
#define FLB_KS 9216
#define FLB_VT 27648
#define FLB_MS 41472
#define FLB_PS 76288
#define FLB_TOTAL 85504

__global__ __launch_bounds__(128) void flash_kernel(
    const hf* __restrict__ q, const hf* __restrict__ k,
    const hf* __restrict__ vt, const float* __restrict__ mask,
    float* __restrict__ po, float* __restrict__ pm, float* __restrict__ pl) {
    extern __shared__ char smc[];
    hf* Qs = reinterpret_cast<hf*>(smc + FLB_QS);
    hf* Ps = reinterpret_cast<hf*>(smc + FLB_PS);
    int t = threadIdx.x;
    int wid = t >> 5, lane = t & 31, grp = lane >> 2, tig = lane & 3;
    int t0 = blockIdx.x * 64;
    int h  = blockIdx.y;
    int rsp = blockIdx.z;
    int rbase = rsp * (N_RES / RSPLIT);
    int wr = wid * 16;

    for (int i = t; i < 64 * 6; i += 128) {
        int r = i / 6, f = i % 6;
        *reinterpret_cast<uint4*>(&Qs[r * HP + f * 8]) =
            *reinterpret_cast<const uint4*>(&q[(size_t)(t0 + r) * C_DIM + h * KD + f * 8]);
    }

    const int NCH = (N_RES / RSPLIT) / RCHUNK;

    auto issue = [&](int ch, int b) {
        int r0 = rbase + ch * RCHUNK;
        hf*    ks  = reinterpret_cast<hf*>(smc + FLB_KS) + b * 64 * HP;
        hf*    vts = reinterpret_cast<hf*>(smc + FLB_VT) + b * 48 * HP;
        float* ms  = reinterpret_cast<float*>(smc + FLB_MS) + b * 64 * MS_PITCH;
        for (int i = t; i < 64 * 6; i += 128) {
            int r = i / 6, f = i % 6;
            cp16(&ks[r * HP + f * 8], &k[(size_t)(r0 + r) * C_DIM + h * KD + f * 8]);
        }
        for (int i = t; i < 48 * 8; i += 128) {
            int c = i >> 3, g = i & 7;
            cp16(&vts[c * HP + g * 8], &vt[(size_t)(h * KD + c) * N_RES + r0 + g * 8]);
        }
        for (int i = t; i < 64 * 16; i += 128) {
            int rr = i / 16, f = i % 16;
            cp16(&ms[rr * MS_PITCH + f * 4],
                 &mask[((size_t)h * T_TOK + t0 + rr) * N_RES + r0 + f * 4]);
        }
    };

    issue(0, 0); CP_COMMIT();
    issue(1, 1); CP_COMMIT();

    float m_lo = -1e30f, m_hi = -1e30f, l_lo = 0.0f, l_hi = 0.0f;
    float acc_o[6][4];
    #pragma unroll
    for (int i = 0; i < 6; i++)
        #pragma unroll
        for (int e = 0; e < 4; e++) acc_o[i][e] = 0.0f;

    for (int ch = 0; ch < NCH; ch++) {
        int b = ch & 1;
        CP_WAIT(1);
        __syncthreads();
        hf*    ks  = reinterpret_cast<hf*>(smc + FLB_KS) + b * 64 * HP;
        hf*    vts = reinterpret_cast<hf*>(smc + FLB_VT) + b * 48 * HP;
        float* ms  = reinterpret_cast<float*>(smc + FLB_MS) + b * 64 * MS_PITCH;

        // S = Q @ K^T : 3 fp16 k16-steps
        float acc_s[8][4];
        #pragma unroll
        for (int fn = 0; fn < 8; fn++)
            #pragma unroll
            for (int e = 0; e < 4; e++) acc_s[fn][e] = 0.0f;
        #pragma unroll
        for (int s = 0; s < 3; s++) {
            int k0 = s * 16;
            unsigned a[4];
            a[0] = *reinterpret_cast<const unsigned*>(Qs + (wr + grp) * HP + k0 + 2 * tig);
            a[1] = *reinterpret_cast<const unsigned*>(Qs + (wr + grp + 8) * HP + k0 + 2 * tig);
            a[2] = *reinterpret_cast<const unsigned*>(Qs + (wr + grp) * HP + k0 + 8 + 2 * tig);
            a[3] = *reinterpret_cast<const unsigned*>(Qs + (wr + grp + 8) * HP + k0 + 8 + 2 * tig);
            #pragma unroll
            for (int fn = 0; fn < 8; fn++) {
                unsigned bb[2];
                bb[0] = *reinterpret_cast<const unsigned*>(ks + (fn * 8 + grp) * HP + k0 + 2 * tig);
                bb[1] = *reinterpret_cast<const unsigned*>(ks + (fn * 8 + grp) * HP + k0 + 8 + 2 * tig);
                MMA_F16(acc_s[fn], a, bb);
            }
        }
        float mx_lo = -1e30f, mx_hi = -1e30f;
        #pragma unroll
        for (int fn = 0; fn < 8; fn++) {
            int col = fn * 8 + 2 * tig;
            float2 blo = *reinterpret_cast<float2*>(&ms[(wr + grp) * MS_PITCH + col]);
            float2 bhi = *reinterpret_cast<float2*>(&ms[(wr + grp + 8) * MS_PITCH + col]);
            acc_s[fn][0] += BIGF * (blo.x - 1.0f);
            acc_s[fn][1] += BIGF * (blo.y - 1.0f);
            acc_s[fn][2] += BIGF * (bhi.x - 1.0f);
            acc_s[fn][3] += BIGF * (bhi.y - 1.0f);
            mx_lo = fmaxf(mx_lo, fmaxf(acc_s[fn][0], acc_s[fn][1]));
            mx_hi = fmaxf(mx_hi, fmaxf(acc_s[fn][2], acc_s[fn][3]));
        }
        mx_lo = fmaxf(mx_lo, __shfl_xor_sync(0xffffffffu, mx_lo, 1));
        mx_lo = fmaxf(mx_lo, __shfl_xor_sync(0xffffffffu, mx_lo, 2));
        mx_hi = fmaxf(mx_hi, __shfl_xor_sync(0xffffffffu, mx_hi, 1));
        mx_hi = fmaxf(mx_hi, __shfl_xor_sync(0xffffffffu, mx_hi, 2));
        float mn_lo = fmaxf(m_lo, mx_lo), mn_hi = fmaxf(m_hi, mx_hi);
        float sc_lo = __expf(m_lo - mn_lo), sc_hi = __expf(m_hi - mn_hi);
        m_lo = mn_lo; m_hi = mn_hi;
        float rs_lo = 0.0f, rs_hi = 0.0f;
        #pragma unroll
        for (int fn = 0; fn < 8; fn++) {
            int col = fn * 8 + 2 * tig;
            float p0 = __expf(acc_s[fn][0] - mn_lo);
            float p1 = __expf(acc_s[fn][1] - mn_lo);
            float p2 = __expf(acc_s[fn][2] - mn_hi);
            float p3 = __expf(acc_s[fn][3] - mn_hi);
            rs_lo += p0 + p1; rs_hi += p2 + p3;
            *reinterpret_cast<__half2*>(Ps + (wr + grp) * HP + col) = __floats2half2_rn(p0, p1);
            *reinterpret_cast<__half2*>(Ps + (wr + grp + 8) * HP + col) = __floats2half2_rn(p2, p3);
        }
        rs_lo += __shfl_xor_sync(0xffffffffu, rs_lo, 1);
        rs_lo += __shfl_xor_sync(0xffffffffu, rs_lo, 2);
        rs_hi += __shfl_xor_sync(0xffffffffu, rs_hi, 1);
        rs_hi += __shfl_xor_sync(0xffffffffu, rs_hi, 2);
        l_lo = l_lo * sc_lo + rs_lo;
        l_hi = l_hi * sc_hi + rs_hi;
        #pragma unroll
        for (int fn = 0; fn < 6; fn++) {
            acc_o[fn][0] *= sc_lo; acc_o[fn][1] *= sc_lo;
            acc_o[fn][2] *= sc_hi; acc_o[fn][3] *= sc_hi;
        }
        __syncwarp();   // P rows are warp-private; warp-level sync suffices
        // O += P @ V : 4 fp16 k16-steps over r
        #pragma unroll
        for (int s = 0; s < 4; s++) {
            int k0 = s * 16;
            unsigned a[4];
            a[0] = *reinterpret_cast<const unsigned*>(Ps + (wr + grp) * HP + k0 + 2 * tig);
            a[1] = *reinterpret_cast<const unsigned*>(Ps + (wr + grp + 8) * HP + k0 + 2 * tig);
            a[2] = *reinterpret_cast<const unsigned*>(Ps + (wr + grp) * HP + k0 + 8 + 2 * tig);
            a[3] = *reinterpret_cast<const unsigned*>(Ps + (wr + grp + 8) * HP + k0 + 8 + 2 * tig);
            #pragma unroll
            for (int fn = 0; fn < 6; fn++) {
                unsigned bb[2];
                bb[0] = *reinterpret_cast<const unsigned*>(vts + (fn * 8 + grp) * HP + k0 + 2 * tig);
                bb[1] = *reinterpret_cast<const unsigned*>(vts + (fn * 8 + grp) * HP + k0 + 8 + 2 * tig);
                MMA_F16(acc_o[fn], a, bb);
            }
        }
        __syncthreads();
        if (ch + 2 < NCH) issue(ch + 2, b);
        CP_COMMIT();
    }

    int row_lo = (rsp * H_HEADS + h) * T_TOK + t0 + wr + grp;
    int row_hi = row_lo + 8;
    #pragma unroll
    for (int fn = 0; fn < 6; fn++) {
        int c = fn * 8 + 2 * tig;
        *reinterpret_cast<float2*>(&po[(size_t)row_lo * KD + c]) =
            make_float2(acc_o[fn][0], acc_o[fn][1]);
        *reinterpret_cast<float2*>(&po[(size_t)row_hi * KD + c]) =
            make_float2(acc_o[fn][2], acc_o[fn][3]);
    }
    if (tig == 0) {
        pm[row_lo] = m_lo; pm[row_hi] = m_hi;
        pl[row_lo] = l_lo; pl[row_hi] = l_hi;
    }
}

// ---------------- combine r-splits, apply gate, write wag fp16 ----------------
__global__ void combine_kernel(const float* __restrict__ po, const float* __restrict__ pm,
                               const float* __restrict__ pl, const float* __restrict__ gate,
                               hf* __restrict__ wag) {
    int idx = blockIdx.x * 256 + threadIdx.x;
    const int TOT = H_HEADS * T_TOK * KD;
    const int HT  = H_HEADS * T_TOK;
    if (idx >= TOT) return;
    int c  = idx % KD;
    int ht = idx / KD;
    int tt = ht % T_TOK, h = ht / T_TOK;
    float mm = -1e30f;
    #pragma unroll
    for (int r = 0; r < RSPLIT; r++) mm = fmaxf(mm, pm[r * HT + ht]);
    float l = 0.0f, o = 0.0f;
    #pragma unroll
    for (int r = 0; r < RSPLIT; r++) {
        float s = __expf(pm[r * HT + ht] - mm);
        l += pl[r * HT + ht] * s;
        o += po[(size_t)r * TOT + idx] * s;
    }
    o /= l;
    float g = gate[(size_t)tt * C_DIM + h * KD + c];
    wag[(size_t)tt * C_DIM + h * KD + c] = __float2half_rn(o * g);
}

// ---------------- host launch ----------------
static void* symv(const void* s) {
    void* p = nullptr;
    cudaGetSymbolAddress(&p, s);
    return p;
}

extern "C" void kernel_launch(void* const* d_in, const int* in_sizes, int n_in,
                              void* d_out, int out_size) {
    const float* original   = (const float*)d_in[0];
    const float* resampled  = (const float*)d_in[1];
    const float* attn_mask  = (const float*)d_in[2];
    const float* qn_scale   = (const float*)d_in[5];
    const float* qn_offset  = (const float*)d_in[6];
    const float* dn_scale   = (const float*)d_in[7];
    const float* dn_offset  = (const float*)d_in[8];
    const float* query_w    = (const float*)d_in[9];
    const float* key_w      = (const float*)d_in[10];
    const float* value_w    = (const float*)d_in[11];
    const float* gating_w   = (const float*)d_in[12];
    const float* gating_b   = (const float*)d_in[13];
    const float* output_w   = (const float*)d_in[14];
    const float* output_b   = (const float*)d_in[15];
    const float* rt_ln_scale  = (const float*)d_in[16];
    const float* rt_ln_offset = (const float*)d_in[17];
    const float* rt_w1 = (const float*)d_in[18];
    const float* rt_b1 = (const float*)d_in[19];
    const float* rt_w2 = (const float*)d_in[20];
    const float* rt_b2 = (const float*)d_in[21];
    const float* ot_ln_scale  = (const float*)d_in[22];
    const float* ot_ln_offset = (const float*)d_in[23];
    const float* ot_w1 = (const float*)d_in[24];
    const float* ot_b1 = (const float*)d_in[25];
    const float* ot_w2 = (const float*)d_in[26];
    const float* ot_b2 = (const float*)d_in[27];

    float* out_res  = (float*)d_out;
    float* out_orig = out_res + (size_t)T_TOK * C_DIM;

    hf*    p_qin  = (hf*)symv(g_qin);
    hf*    p_din  = (hf*)symv(g_din);
    hf*    p_ln4  = (hf*)symv(g_ln4);
    hf*    p_qh   = (hf*)symv(g_qh);
    hf*    p_kh   = (hf*)symv(g_kh);
    hf*    p_vt   = (hf*)symv(g_vt);
    float* p_gate = (float*)symv(g_gate);
    hf*    p_wag  = (hf*)symv(g_wag);
    hf*    p_ln3  = (hf*)symv(g_ln3);
    hf*    p_h1   = (hf*)symv(g_h1);
    hf*    p_h2   = (hf*)symv(g_h2);
    float* p_part = (float*)symv(g_part);
    hf*    p_wts  = (hf*)symv(g_wts);
    float* p_po   = (float*)symv(g_po);
    float* p_pm   = (float*)symv(g_pm);
    float* p_pl   = (float*)symv(g_pl);

    const int smem128 = STAGES * (128 * BK + 128 * BK) * 2;   // 65536 B
    const int smem64  = STAGES * (64 * BK + 128 * BK) * 2;    // 49152 B
    const int flash_smem = FLB_TOTAL;                         // 85504 B
    cudaFuncSetAttribute(gemm_hf<128>, cudaFuncAttributeMaxDynamicSharedMemorySize, smem128);
    cudaFuncSetAttribute(gemm_hf<64>,  cudaFuncAttributeMaxDynamicSharedMemorySize, smem64);
    cudaFuncSetAttribute(flash_kernel, cudaFuncAttributeMaxDynamicSharedMemorySize, flash_smem);

    const float inv_sqrt_kd = 0.14433756729740643f;
    const int BIG_HALF = 1 << 30;
    const int KH = F_DIM / 2;    // 768 split-K half

    cudaStream_t s2 = 0;
    cudaEvent_t ev_root = 0, ev_ln = 0, ev_w = 0, ev_ot = 0;
    cudaStreamCreateWithFlags(&s2, cudaStreamNonBlocking);
    cudaEventCreateWithFlags(&ev_root, cudaEventDisableTiming);
    cudaEventCreateWithFlags(&ev_ln, cudaEventDisableTiming);
    cudaEventCreateWithFlags(&ev_w,  cudaEventDisableTiming);
    cudaEventCreateWithFlags(&ev_ot, cudaEventDisableTiming);
    bool fork_ok = s2 && ev_root && ev_ln && ev_w && ev_ot;

    SrcPtrs sp;
    sp.p[0] = query_w;  sp.p[1] = key_w;  sp.p[2] = value_w;
    sp.p[3] = gating_w; sp.p[4] = output_w;
    sp.p[5] = rt_w1;    sp.p[6] = rt_w2;  sp.p[7] = ot_w1; sp.p[8] = ot_w2;

    if (fork_ok) {
        cudaEventRecord(ev_root, 0);
        cudaStreamWaitEvent(s2, ev_root, 0);

        wt_kernel<<<3024, 256, 0, s2>>>(sp, p_wts);
        cudaEventRecord(ev_w, s2);

        ln_fused_kernel<<<T_TOK + 2 * N_RES, 128>>>(resampled, original,
            qn_scale, qn_offset, dn_scale, dn_offset, ot_ln_scale, ot_ln_offset,
            p_qin, p_din, p_ln4);
        cudaEventRecord(ev_ln, 0);

        cudaStreamWaitEvent(s2, ev_ln, 0);
        gemm_hf<128><<<dim3(12, 32), 256, smem128, s2>>>(p_ln4,
            p_wts + OFF_OT1, p_h2, 1.0f, ot_b1, ACT_RELU, nullptr, 2,
            p_ln4, nullptr, nullptr, 0.0f, nullptr, 0, nullptr, 0,
            N_RES, F_DIM, C_DIM, C_DIM, BIG_HALF);
        // ot2 split-K: half0 -> out_orig (bias+residual); half1 -> raw partial
        gemm_hf<64><<<dim3(6, 64), 256, smem64, s2>>>(p_h2,
            p_wts + OFF_OT2, out_orig, 1.0f, ot_b2, ACT_NONE, original, 0,
            p_h2 + KH, p_wts + OFF_OT2 + KH, p_part, 1.0f, nullptr, ACT_NONE, nullptr, 0,
            N_RES, C_DIM, F_DIM, KH, 3);
        add_kernel<<<(N_RES * C_DIM / 4 + 255) / 256, 256, 0, s2>>>(
            out_orig, p_part, N_RES * C_DIM / 4);
        cudaEventRecord(ev_ot, s2);

        cudaStreamWaitEvent(0, ev_w, 0);
    } else {
        wt_kernel<<<3024, 256>>>(sp, p_wts);
        ln_fused_kernel<<<T_TOK + 2 * N_RES, 128>>>(resampled, original,
            qn_scale, qn_offset, dn_scale, dn_offset, ot_ln_scale, ot_ln_offset,
            p_qin, p_din, p_ln4);
        gemm_hf<128><<<dim3(12, 32), 256, smem128>>>(p_ln4,
            p_wts + OFF_OT1, p_h2, 1.0f, ot_b1, ACT_RELU, nullptr, 2,
            p_ln4, nullptr, nullptr, 0.0f, nullptr, 0, nullptr, 0,
            N_RES, F_DIM, C_DIM, C_DIM, BIG_HALF);
        gemm_hf<64><<<dim3(6, 64), 256, smem64>>>(p_h2,
            p_wts + OFF_OT2, out_orig, 1.0f, ot_b2, ACT_NONE, original, 0,
            p_h2 + KH, p_wts + OFF_OT2 + KH, p_part, 1.0f, nullptr, ACT_NONE, nullptr, 0,
            N_RES, C_DIM, F_DIM, KH, 3);
        add_kernel<<<(N_RES * C_DIM / 4 + 255) / 256, 256>>>(
            out_orig, p_part, N_RES * C_DIM / 4);
    }

    // main chain: q fp16 + gate f32; k fp16 + V^T fp16 (transposed epilogue)
    gemm_hf<64><<<dim3(6, 8), 256, smem64>>>(p_qin,
        p_wts + OFF_QW, p_qh, inv_sqrt_kd, nullptr, ACT_NONE, nullptr, 2,
        p_qin, p_wts + OFF_GW, p_gate, 1.0f, gating_b, ACT_SIGMOID, nullptr, 0,
        T_TOK, C_DIM, C_DIM, C_DIM, 3);
    gemm_hf<128><<<dim3(6, 32), 256, smem128>>>(p_din,
        p_wts + OFF_KW, p_kh, 1.0f, nullptr, ACT_NONE, nullptr, 2,
        p_din, p_wts + OFF_VW, p_vt, 1.0f, nullptr, ACT_NONE, nullptr, 4,
        N_RES, C_DIM, C_DIM, C_DIM, 3);

    flash_kernel<<<dim3(T_TOK / 64, H_HEADS, RSPLIT), 128, flash_smem>>>(
        p_qh, p_kh, p_vt, attn_mask, p_po, p_pm, p_pl);
    combine_kernel<<<(H_HEADS * T_TOK * KD + 255) / 256, 256>>>(p_po, p_pm, p_pl, p_gate, p_wag);

    gemm_hf<64><<<dim3(3, 8), 256, smem64>>>(p_wag,
        p_wts + OFF_OW, out_res, 1.0f, output_b, ACT_NONE, resampled, 0,
        p_wag, nullptr, nullptr, 0.0f, nullptr, 0, nullptr, 0,
        T_TOK, C_DIM, C_DIM, C_DIM, BIG_HALF);

    ln_kernel<<<T_TOK, 128>>>(out_res, rt_ln_scale, rt_ln_offset, p_ln3);
    gemm_hf<64><<<dim3(12, 8), 256, smem64>>>(p_ln3,
        p_wts + OFF_RT1, p_h1, 1.0f, rt_b1, ACT_RELU, nullptr, 2,
        p_ln3, nullptr, nullptr, 0.0f, nullptr, 0, nullptr, 0,
        T_TOK, F_DIM, C_DIM, C_DIM, BIG_HALF);
    gemm_hf<64><<<dim3(3, 8), 256, smem64>>>(p_h1,
        p_wts + OFF_RT2, out_res, 1.0f, rt_b2, ACT_NONE, out_res, 0,
        p_h1, nullptr, nullptr, 0.0f, nullptr, 0, nullptr, 0,
        T_TOK, C_DIM, F_DIM, F_DIM, BIG_HALF);

    if (fork_ok) cudaStreamWaitEvent(0, ev_ot, 0);
}